// round 6
// baseline (speedup 1.0000x reference)
#include <cuda_runtime.h>
#include <cuda_bf16.h>
#include <stdint.h>

// Problem constants
#define BATCH 256
#define M 128
#define NIMG 100
#define NP 104          // 13 * 8
#define D 768
#define ITERS 50
#define THREADS 512

// Staging layout (per buffer, swizzled bf16, 128B rows)
#define XHI_OFF 0u
#define XLO_OFF 16384u
#define YHI_OFF 32768u
#define YLO_OFF 46080u
#define BUF_BYTES 59392u
#define DSM_GEMM (2 * 59392 + 1024)

#define SWZ(o) ((o) ^ (((o) >> 3) & 0x70))

// A stored in per-thread fragment layout:
// g_A[((b*16 + w)*7 + ti)*128 + lane*4 + e], e=0..3  (s=1 warps use ti<6)
__device__ __align__(16) float g_A[BATCH * 16 * 7 * 128];
__device__ float g_ot[BATCH];
__device__ int   g_isU8;

// ---------------------------------------------------------------------------
// Helpers
// ---------------------------------------------------------------------------
__device__ __forceinline__ uint32_t smem_u32(const void* p) {
    uint32_t a;
    asm("{ .reg .u64 t; cvta.to.shared.u64 t, %1; cvt.u32.u64 %0, t; }"
        : "=r"(a) : "l"(p));
    return a;
}
__device__ __forceinline__ void ldsm4(uint32_t addr, uint32_t* r) {
    asm volatile("ldmatrix.sync.aligned.m8n8.x4.shared.b16 {%0,%1,%2,%3}, [%4];"
                 : "=r"(r[0]), "=r"(r[1]), "=r"(r[2]), "=r"(r[3]) : "r"(addr));
}
__device__ __forceinline__ void mma_bf16(float* d, const uint32_t* a,
                                         uint32_t b0, uint32_t b1) {
    asm volatile(
        "mma.sync.aligned.m16n8k16.row.col.f32.bf16.bf16.f32 "
        "{%0,%1,%2,%3},{%4,%5,%6,%7},{%8,%9},{%0,%1,%2,%3};"
        : "+f"(d[0]), "+f"(d[1]), "+f"(d[2]), "+f"(d[3])
        : "r"(a[0]), "r"(a[1]), "r"(a[2]), "r"(a[3]), "r"(b0), "r"(b1));
}
// Split a,b into bf16-hi pair + fp32-residual bf16 pair. lo halfword = a.
__device__ __forceinline__ void split2(float a, float b, uint32_t& hi, uint32_t& lo) {
    asm("cvt.rn.bf16x2.f32 %0, %1, %2;" : "=r"(hi) : "f"(b), "f"(a));
    float ah = __uint_as_float(hi << 16);
    float bh = __uint_as_float(hi & 0xffff0000u);
    float la = a - ah, lb = b - bh;
    asm("cvt.rn.bf16x2.f32 %0, %1, %2;" : "=r"(lo) : "f"(lb), "f"(la));
}

__global__ void k_nop() {}

// ---------------------------------------------------------------------------
// Pad-dtype detect (uint8-bool vs int32): any nonzero byte at p%4!=0 => u8.
// ---------------------------------------------------------------------------
__global__ void __launch_bounds__(512) k_detect(const unsigned char* __restrict__ tp,
                                                const unsigned char* __restrict__ ip) {
    __shared__ int sflag;
    int tid = threadIdx.x;
    if (tid == 0) sflag = 0;
    __syncthreads();
    uint32_t acc = 0;
    const uint4* t4 = (const uint4*)tp;
    for (int i = tid; i < 2048; i += 512) {
        uint4 v = t4[i];
        acc |= (v.x | v.y | v.z | v.w) & 0xFFFFFF00u;
    }
    const uint4* i4 = (const uint4*)ip;
    for (int i = tid; i < 1600; i += 512) {
        uint4 v = i4[i];
        acc |= (v.x | v.y | v.z | v.w) & 0xFFFFFF00u;
    }
    uint32_t any = __ballot_sync(0xffffffffu, acc != 0);
    if ((tid & 31) == 0 && any) atomicOr(&sflag, 1);
    __syncthreads();
    if (tid == 0) g_isU8 = sflag;
}

// ---------------------------------------------------------------------------
// GEMM kernel: split-bf16 mma.sync, double-buffered staging, epilogue writes
// A = exp(2*(cos_sim - 1)) (masked) to g_A in fragment layout.
// Warp w: row-group r=w>>1 (m 16r..16r+15), slot s=w&1 owns tiles
// t = s*7 .. s*7+NT-1 (NT = 7-s).
// ---------------------------------------------------------------------------
__global__ void __launch_bounds__(THREADS) k_gemm(const float* __restrict__ seq,
                                                  const unsigned char* __restrict__ tp,
                                                  const unsigned char* __restrict__ ip) {
    extern __shared__ __align__(16) char dsm[];
    __shared__ float pSq[928];
    __shared__ float sNxi[M], sNyi[NP];
    __shared__ float sXm[M], sYm[NP];

    const int b = blockIdx.x, tid = threadIdx.x;
    const int lane = tid & 31, w = tid >> 5;
    const int g = lane >> 2, q2 = lane & 3;
    const int r = w >> 1, s = w & 1;
    const int TBASE = s * 7, NT = 7 - s;

    uint32_t rawb = smem_u32(dsm);
    uint32_t sb = (rawb + 1023u) & ~1023u;
    char* sbuf = dsm + (sb - rawb);

    // masks (no length counting here)
    const int u8 = g_isU8;
    if (tid < M) {
        int pad = u8 ? (tp[b * M + tid] != 0) : (((const int*)tp)[b * M + tid] != 0);
        sXm[tid] = pad ? 1e4f : 0.f;
    }
    if (tid < NP) {
        int pad = (tid >= NIMG) ? 1
                : (u8 ? (ip[b * NIMG + tid] != 0) : (((const int*)ip)[b * NIMG + tid] != 0));
        sYm[tid] = pad ? 1e4f : 0.f;
    }

    const float* seqb = seq + (size_t)b * 228 * D;
    const int row = tid >> 2, seg = tid & 3;
    const int hasY = tid < 416;
    const float* px = seqb + (size_t)row * D + seg * 16;
    const float* py = (hasY && row < NIMG)
                    ? (seqb + (size_t)(128 + row) * D + seg * 16) : nullptr;
    const uint32_t off0 = (uint32_t)(row * 128 + seg * 32);
    const uint32_t swz0 = SWZ(off0), swz1 = SWZ(off0 + 16);

    const int j8 = lane >> 3, sub = lane & 7;
    const uint32_t arow_off = (uint32_t)((16 * r + ((j8 & 1) << 3) + sub) * 128);
    const int acol = (j8 >> 1) * 8;
    const int bcol = j8 * 8;

    float acc[28];
#pragma unroll
    for (int i = 0; i < 28; i++) acc[i] = 0.f;
    float nacc0 = 0.f, nacc1 = 0.f;

    float4 vx[4], vy[4];
    {
        const float4* p4 = (const float4*)px;
        vx[0] = p4[0]; vx[1] = p4[1]; vx[2] = p4[2]; vx[3] = p4[3];
        if (hasY) {
            if (py) { const float4* q4 = (const float4*)py;
                      vy[0] = q4[0]; vy[1] = q4[1]; vy[2] = q4[2]; vy[3] = q4[3]; }
            else vy[0] = vy[1] = vy[2] = vy[3] = make_float4(0.f, 0.f, 0.f, 0.f);
        }
    }

    for (int c = 0; c < 12; c++) {
        char* bb = sbuf + (uint32_t)(c & 1) * BUF_BYTES;
        {
            float ss = 0.f;
#pragma unroll
            for (int h = 0; h < 2; h++) {
                float4 f0 = vx[2 * h], f1 = vx[2 * h + 1];
                ss += f0.x*f0.x + f0.y*f0.y + f0.z*f0.z + f0.w*f0.w
                    + f1.x*f1.x + f1.y*f1.y + f1.z*f1.z + f1.w*f1.w;
                uint4 hi, lo;
                split2(f0.x, f0.y, hi.x, lo.x);
                split2(f0.z, f0.w, hi.y, lo.y);
                split2(f1.x, f1.y, hi.z, lo.z);
                split2(f1.z, f1.w, hi.w, lo.w);
                uint32_t sw = h ? swz1 : swz0;
                *(uint4*)(bb + XHI_OFF + sw) = hi;
                *(uint4*)(bb + XLO_OFF + sw) = lo;
            }
            nacc0 += ss;
        }
        if (hasY) {
            float ss = 0.f;
#pragma unroll
            for (int h = 0; h < 2; h++) {
                float4 f0 = vy[2 * h], f1 = vy[2 * h + 1];
                ss += f0.x*f0.x + f0.y*f0.y + f0.z*f0.z + f0.w*f0.w
                    + f1.x*f1.x + f1.y*f1.y + f1.z*f1.z + f1.w*f1.w;
                uint4 hi, lo;
                split2(f0.x, f0.y, hi.x, lo.x);
                split2(f0.z, f0.w, hi.y, lo.y);
                split2(f1.x, f1.y, hi.z, lo.z);
                split2(f1.z, f1.w, hi.w, lo.w);
                uint32_t sw = h ? swz1 : swz0;
                *(uint4*)(bb + YHI_OFF + sw) = hi;
                *(uint4*)(bb + YLO_OFF + sw) = lo;
            }
            nacc1 += ss;
        }
        __syncthreads();

        if (c < 11) {
            const float4* p4 = (const float4*)(px + (c + 1) * 64);
            vx[0] = p4[0]; vx[1] = p4[1]; vx[2] = p4[2]; vx[3] = p4[3];
            if (hasY) {
                if (py) { const float4* q4 = (const float4*)(py + (c + 1) * 64);
                          vy[0] = q4[0]; vy[1] = q4[1]; vy[2] = q4[2]; vy[3] = q4[3]; }
                else vy[0] = vy[1] = vy[2] = vy[3] = make_float4(0.f, 0.f, 0.f, 0.f);
            }
        }

        uint32_t bbase = sb + (uint32_t)(c & 1) * BUF_BYTES;
#pragma unroll
        for (int k0 = 0; k0 < 64; k0 += 32) {
            uint32_t ah0[4], ah1[4], al0[4], al1[4];
            uint32_t offA0 = SWZ(arow_off + (uint32_t)((k0 + acol) * 2));
            uint32_t offA1 = SWZ(arow_off + (uint32_t)((k0 + 16 + acol) * 2));
            ldsm4(bbase + XHI_OFF + offA0, ah0);
            ldsm4(bbase + XHI_OFF + offA1, ah1);
            ldsm4(bbase + XLO_OFF + offA0, al0);
            ldsm4(bbase + XLO_OFF + offA1, al1);
#pragma unroll
            for (int ti = 0; ti < 7; ti++) {
                if (ti < NT) {
                    int t = TBASE + ti;
                    uint32_t offB = SWZ((uint32_t)((8 * t + sub) * 128 + (k0 + bcol) * 2));
                    uint32_t bh[4], bl[4];
                    ldsm4(bbase + YHI_OFF + offB, bh);
                    ldsm4(bbase + YLO_OFF + offB, bl);
                    float* d = &acc[ti * 4];
                    mma_bf16(d, ah0, bh[0], bh[1]);
                    mma_bf16(d, al0, bh[0], bh[1]);
                    mma_bf16(d, ah0, bl[0], bl[1]);
                    mma_bf16(d, ah1, bh[2], bh[3]);
                    mma_bf16(d, al1, bh[2], bh[3]);
                    mma_bf16(d, ah1, bl[2], bl[3]);
                }
            }
        }
    }

    // norms
    pSq[tid] = nacc0;
    if (hasY) pSq[512 + tid] = nacc1;
    __syncthreads();
    if (tid < M) {
        float ss = pSq[4 * tid] + pSq[4 * tid + 1] + pSq[4 * tid + 2] + pSq[4 * tid + 3];
        sNxi[tid] = 1.f / fmaxf(sqrtf(ss), 1e-5f);
    } else if (tid < M + NP) {
        int n = tid - M;
        float ss = pSq[512 + 4 * n] + pSq[512 + 4 * n + 1]
                 + pSq[512 + 4 * n + 2] + pSq[512 + 4 * n + 3];
        sNyi[n] = 1.f / fmaxf(sqrtf(ss), 1e-5f);
    }
    __syncthreads();

    // epilogue -> g_A (fragment layout, coalesced float4)
    const int m0 = 16 * r + g, m1 = m0 + 8;
    const float xm0 = sXm[m0], xm1 = sXm[m1];
    const float nx0 = sNxi[m0], nx1 = sNxi[m1];
    float* gA = g_A + ((size_t)(b * 16 + w) * 7) * 128;
#pragma unroll
    for (int ti = 0; ti < 7; ti++) {
        if (ti < NT) {
            int t = TBASE + ti;
            int n0 = 8 * t + 2 * q2, n1 = n0 + 1;
            float ny0 = sNyi[n0], ny1 = sNyi[n1];
            float ym0 = sYm[n0],  ym1 = sYm[n1];
            float4 a;
            a.x = (xm0 > 0.f || ym0 > 0.f) ? 0.f
                : __expf(2.f * (acc[ti * 4 + 0] * nx0 * ny0 - 1.f));
            a.y = (xm0 > 0.f || ym1 > 0.f) ? 0.f
                : __expf(2.f * (acc[ti * 4 + 1] * nx0 * ny1 - 1.f));
            a.z = (xm1 > 0.f || ym0 > 0.f) ? 0.f
                : __expf(2.f * (acc[ti * 4 + 2] * nx1 * ny0 - 1.f));
            a.w = (xm1 > 0.f || ym1 > 0.f) ? 0.f
                : __expf(2.f * (acc[ti * 4 + 3] * nx1 * ny1 - 1.f));
            *(float4*)(gA + ti * 128 + lane * 4) = a;
        }
    }
}

// ---------------------------------------------------------------------------
// IPOT kernel: loads A fragments (register-resident), 50 iterations, reduce.
// Same warp/fragment geometry as k_gemm. ~95 regs -> no spills.
// ---------------------------------------------------------------------------
__global__ void __launch_bounds__(THREADS) k_ipot(const unsigned char* __restrict__ tp,
                                                  const unsigned char* __restrict__ ip) {
    __shared__ float sXm[M], sYm[NP];
    __shared__ __align__(8) float sDelta[NP];
    __shared__ __align__(8) float sQsPart[8 * NP];
    __shared__ __align__(8) float sPartM[M * 2];
    __shared__ float sRed[16];
    __shared__ int sCx, sCy;

    const int b = blockIdx.x, tid = threadIdx.x;
    const int lane = tid & 31, w = tid >> 5;
    const int g = lane >> 2, q2 = lane & 3;
    const int r = w >> 1, s = w & 1;
    const int TBASE = s * 7, NT = 7 - s;

    if (tid == 0) { sCx = 0; sCy = 0; }
    __syncthreads();
    const int u8 = g_isU8;
    if (tid < M) {
        int pad = u8 ? (tp[b * M + tid] != 0) : (((const int*)tp)[b * M + tid] != 0);
        sXm[tid] = pad ? 1e4f : 0.f;
        if (pad) atomicAdd(&sCx, 1);
    }
    if (tid < NP) {
        int pad = (tid >= NIMG) ? 1
                : (u8 ? (ip[b * NIMG + tid] != 0) : (((const int*)ip)[b * NIMG + tid] != 0));
        sYm[tid] = pad ? 1e4f : 0.f;
        if (pad && tid < NIMG) atomicAdd(&sCy, 1);
    }
    __syncthreads();

    // load A fragments
    float acc[28], Qr[28];
    const float* gA = g_A + ((size_t)(b * 16 + w) * 7) * 128;
#pragma unroll
    for (int ti = 0; ti < 7; ti++) {
        if (ti < NT) {
            float4 a = *(const float4*)(gA + ti * 128 + lane * 4);
            acc[ti * 4 + 0] = a.x; Qr[ti * 4 + 0] = a.x;
            acc[ti * 4 + 1] = a.y; Qr[ti * 4 + 1] = a.y;
            acc[ti * 4 + 2] = a.z; Qr[ti * 4 + 2] = a.z;
            acc[ti * 4 + 3] = a.w; Qr[ti * 4 + 3] = a.w;
        }
    }

    const int m0 = 16 * r + g, m1 = m0 + 8;
    const float xm0 = sXm[m0], xm1 = sXm[m1];
    const float xl = (float)(M - sCx), yl = (float)(NIMG - sCy);

    float sig0 = xm0 > 0.f ? 0.f : 1.f / xl;
    float sig1 = xm1 > 0.f ? 0.f : 1.f / xl;

#pragma unroll
    for (int ti = 0; ti < 7; ti++) {
        if (ti < NT) {
            int t = TBASE + ti;
            float qp0 = Qr[ti * 4 + 0] * sig0 + Qr[ti * 4 + 2] * sig1;
            float qp1 = Qr[ti * 4 + 1] * sig0 + Qr[ti * 4 + 3] * sig1;
            qp0 += __shfl_xor_sync(0xffffffffu, qp0, 4);
            qp0 += __shfl_xor_sync(0xffffffffu, qp0, 8);
            qp0 += __shfl_xor_sync(0xffffffffu, qp0, 16);
            qp1 += __shfl_xor_sync(0xffffffffu, qp1, 4);
            qp1 += __shfl_xor_sync(0xffffffffu, qp1, 8);
            qp1 += __shfl_xor_sync(0xffffffffu, qp1, 16);
            if (g == (t & 7))
                *(float2*)&sQsPart[r * NP + 8 * t + 2 * q2] = make_float2(qp0, qp1);
        }
    }
    __syncthreads();

    float ot = 0.f;
#pragma unroll 1
    for (int it = 0; it < ITERS; it++) {
        if (tid < NP) {
            float qs = 0.f;
#pragma unroll
            for (int ww = 0; ww < 8; ww++) qs += sQsPart[ww * NP + tid];
            sDelta[tid] = __fdividef(1.f, yl * qs + sYm[tid]);
        }
        __syncthreads();

        float2 dl[7];
        float p0 = 0.f, p1 = 0.f;
#pragma unroll
        for (int ti = 0; ti < 7; ti++) {
            if (ti < NT) {
                dl[ti] = *(const float2*)&sDelta[8 * (TBASE + ti) + 2 * q2];
                p0 += dl[ti].x * Qr[ti * 4 + 0] + dl[ti].y * Qr[ti * 4 + 1];
                p1 += dl[ti].x * Qr[ti * 4 + 2] + dl[ti].y * Qr[ti * 4 + 3];
            }
        }
        p0 += __shfl_xor_sync(0xffffffffu, p0, 1);
        p0 += __shfl_xor_sync(0xffffffffu, p0, 2);
        p1 += __shfl_xor_sync(0xffffffffu, p1, 1);
        p1 += __shfl_xor_sync(0xffffffffu, p1, 2);
        if (q2 == 0) {
            sPartM[m0 * 2 + s] = p0;
            sPartM[m1 * 2 + s] = p1;
        }
        __syncthreads();
        {
            float2 pm0 = *(const float2*)&sPartM[m0 * 2];
            float2 pm1 = *(const float2*)&sPartM[m1 * 2];
            sig0 = __fdividef(1.f, xl * (pm0.x + pm0.y) + xm0);
            sig1 = __fdividef(1.f, xl * (pm1.x + pm1.y) + xm1);
        }

        if (it < ITERS - 1) {
#pragma unroll
            for (int ti = 0; ti < 7; ti++) {
                if (ti < NT) {
                    int t = TBASE + ti;
                    float q0 = acc[ti * 4 + 0] * Qr[ti * 4 + 0] * (dl[ti].x * sig0);
                    float q1 = acc[ti * 4 + 1] * Qr[ti * 4 + 1] * (dl[ti].y * sig0);
                    float q2v = acc[ti * 4 + 2] * Qr[ti * 4 + 2] * (dl[ti].x * sig1);
                    float q3 = acc[ti * 4 + 3] * Qr[ti * 4 + 3] * (dl[ti].y * sig1);
                    Qr[ti * 4 + 0] = q0; Qr[ti * 4 + 1] = q1;
                    Qr[ti * 4 + 2] = q2v; Qr[ti * 4 + 3] = q3;
                    float qp0 = q0 * sig0 + q2v * sig1;
                    float qp1 = q1 * sig0 + q3 * sig1;
                    qp0 += __shfl_xor_sync(0xffffffffu, qp0, 4);
                    qp0 += __shfl_xor_sync(0xffffffffu, qp0, 8);
                    qp0 += __shfl_xor_sync(0xffffffffu, qp0, 16);
                    qp1 += __shfl_xor_sync(0xffffffffu, qp1, 4);
                    qp1 += __shfl_xor_sync(0xffffffffu, qp1, 8);
                    qp1 += __shfl_xor_sync(0xffffffffu, qp1, 16);
                    if (g == (t & 7))
                        *(float2*)&sQsPart[r * NP + 8 * t + 2 * q2] = make_float2(qp0, qp1);
                }
            }
        } else {
#pragma unroll
            for (int ti = 0; ti < 7; ti++) {
                if (ti < NT) {
                    float a0 = acc[ti * 4 + 0], a1 = acc[ti * 4 + 1];
                    float a2 = acc[ti * 4 + 2], a3 = acc[ti * 4 + 3];
                    if (a0 > 0.f) ot += (-0.5f * __logf(a0)) * Qr[ti * 4 + 0] * dl[ti].x * sig0;
                    if (a1 > 0.f) ot += (-0.5f * __logf(a1)) * Qr[ti * 4 + 1] * dl[ti].y * sig0;
                    if (a2 > 0.f) ot += (-0.5f * __logf(a2)) * Qr[ti * 4 + 2] * dl[ti].x * sig1;
                    if (a3 > 0.f) ot += (-0.5f * __logf(a3)) * Qr[ti * 4 + 3] * dl[ti].y * sig1;
                }
            }
        }
        __syncthreads();
    }

    ot += __shfl_xor_sync(0xffffffffu, ot, 16);
    ot += __shfl_xor_sync(0xffffffffu, ot, 8);
    ot += __shfl_xor_sync(0xffffffffu, ot, 4);
    ot += __shfl_xor_sync(0xffffffffu, ot, 2);
    ot += __shfl_xor_sync(0xffffffffu, ot, 1);
    if (lane == 0) sRed[w] = ot;
    __syncthreads();
    if (tid == 0) {
        float sum = 0.f;
#pragma unroll
        for (int ww = 0; ww < 16; ww++) sum += sRed[ww];
        g_ot[b] = sum;
    }
}

// ---------------------------------------------------------------------------
// Final signed batch reduction -> scalar loss.
// ---------------------------------------------------------------------------
__global__ void k_final(const int* __restrict__ isc, float* __restrict__ out) {
    int t = threadIdx.x;
    __shared__ float sRed[8];
    float v = g_ot[t];
    float s = (isc[t] == 1) ? v : -v;
    s += __shfl_xor_sync(0xffffffffu, s, 16);
    s += __shfl_xor_sync(0xffffffffu, s, 8);
    s += __shfl_xor_sync(0xffffffffu, s, 4);
    s += __shfl_xor_sync(0xffffffffu, s, 2);
    s += __shfl_xor_sync(0xffffffffu, s, 1);
    if ((t & 31) == 0) sRed[t >> 5] = s;
    __syncthreads();
    if (t == 0) {
        float tot = 0.f;
#pragma unroll
        for (int w = 0; w < 8; w++) tot += sRed[w];
        out[0] = tot / (float)BATCH;
    }
}

// ---------------------------------------------------------------------------
extern "C" void kernel_launch(void* const* d_in, const int* in_sizes, int n_in,
                              void* d_out, int out_size) {
    const float* seq = (const float*)d_in[0];
    const unsigned char* tp = (const unsigned char*)d_in[3];
    const unsigned char* ip = (const unsigned char*)d_in[4];
    const int* isc = (const int*)d_in[5];
    float* out = (float*)d_out;

    cudaFuncSetAttribute(k_gemm, cudaFuncAttributeMaxDynamicSharedMemorySize,
                         DSM_GEMM);

    k_detect<<<1, 512>>>(tp, ip);
    k_nop<<<1, 32>>>();   // spacer: k_ipot is profiled launch #4
    k_gemm<<<BATCH, THREADS, DSM_GEMM>>>(seq, tp, ip);
    k_ipot<<<BATCH, THREADS>>>(tp, ip);
    k_final<<<1, 256>>>(isc, out);
}

// round 7
// speedup vs baseline: 1.0969x; 1.0969x over previous
#include <cuda_runtime.h>
#include <cuda_bf16.h>
#include <stdint.h>

// Problem constants
#define BATCH 256
#define M 128
#define NIMG 100
#define NP 104          // 13 * 8
#define D 768
#define ITERS 50
#define GTHREADS 512

// Staging layout (per buffer, swizzled bf16, 128B rows)
#define XHI_OFF 0u
#define XLO_OFF 16384u
#define YHI_OFF 32768u
#define YLO_OFF 46080u
#define BUF_BYTES 59392u
#define DSM_GEMM (2 * 59392 + 1024)
#define DSM_IPOT (NP * M * 4)     // 53248: A matrix blob

#define SWZ(o) ((o) ^ (((o) >> 3) & 0x70))

// A stored as fragment blob in ipot geometry:
// g_A[((b*8 + r)*13 + t)*128 + lane*4 + e]
//   r = m-row-group (warp of 8 in ipot), t = n-tile 0..12, lane/e = mma frag.
__device__ __align__(16) float g_A[BATCH * 8 * 13 * 128];
__device__ float g_ot[BATCH];
__device__ int   g_isU8;

// ---------------------------------------------------------------------------
// Helpers
// ---------------------------------------------------------------------------
__device__ __forceinline__ uint32_t smem_u32(const void* p) {
    uint32_t a;
    asm("{ .reg .u64 t; cvta.to.shared.u64 t, %1; cvt.u32.u64 %0, t; }"
        : "=r"(a) : "l"(p));
    return a;
}
__device__ __forceinline__ void ldsm4(uint32_t addr, uint32_t* r) {
    asm volatile("ldmatrix.sync.aligned.m8n8.x4.shared.b16 {%0,%1,%2,%3}, [%4];"
                 : "=r"(r[0]), "=r"(r[1]), "=r"(r[2]), "=r"(r[3]) : "r"(addr));
}
__device__ __forceinline__ void mma_bf16(float* d, const uint32_t* a,
                                         uint32_t b0, uint32_t b1) {
    asm volatile(
        "mma.sync.aligned.m16n8k16.row.col.f32.bf16.bf16.f32 "
        "{%0,%1,%2,%3},{%4,%5,%6,%7},{%8,%9},{%0,%1,%2,%3};"
        : "+f"(d[0]), "+f"(d[1]), "+f"(d[2]), "+f"(d[3])
        : "r"(a[0]), "r"(a[1]), "r"(a[2]), "r"(a[3]), "r"(b0), "r"(b1));
}
__device__ __forceinline__ void split2(float a, float b, uint32_t& hi, uint32_t& lo) {
    asm("cvt.rn.bf16x2.f32 %0, %1, %2;" : "=r"(hi) : "f"(b), "f"(a));
    float ah = __uint_as_float(hi << 16);
    float bh = __uint_as_float(hi & 0xffff0000u);
    float la = a - ah, lb = b - bh;
    asm("cvt.rn.bf16x2.f32 %0, %1, %2;" : "=r"(lo) : "f"(lb), "f"(la));
}

__global__ void k_nop() {}

// ---------------------------------------------------------------------------
// Pad-dtype detect (uint8-bool vs int32)
// ---------------------------------------------------------------------------
__global__ void __launch_bounds__(512) k_detect(const unsigned char* __restrict__ tp,
                                                const unsigned char* __restrict__ ip) {
    __shared__ int sflag;
    int tid = threadIdx.x;
    if (tid == 0) sflag = 0;
    __syncthreads();
    uint32_t acc = 0;
    const uint4* t4 = (const uint4*)tp;
    for (int i = tid; i < 2048; i += 512) {
        uint4 v = t4[i];
        acc |= (v.x | v.y | v.z | v.w) & 0xFFFFFF00u;
    }
    const uint4* i4 = (const uint4*)ip;
    for (int i = tid; i < 1600; i += 512) {
        uint4 v = i4[i];
        acc |= (v.x | v.y | v.z | v.w) & 0xFFFFFF00u;
    }
    uint32_t any = __ballot_sync(0xffffffffu, acc != 0);
    if ((tid & 31) == 0 && any) atomicOr(&sflag, 1);
    __syncthreads();
    if (tid == 0) g_isU8 = sflag;
}

// ---------------------------------------------------------------------------
// GEMM kernel (unchanged structure): split-bf16 mma.sync, double-buffered
// staging; epilogue writes A to g_A in ipot fragment-blob order.
// Warp w: r=w>>1 (m 16r..16r+15), slot s=w&1 owns tiles t = 7s..7s+NT-1.
// ---------------------------------------------------------------------------
__global__ void __launch_bounds__(GTHREADS) k_gemm(const float* __restrict__ seq,
                                                   const unsigned char* __restrict__ tp,
                                                   const unsigned char* __restrict__ ip) {
    extern __shared__ __align__(16) char dsm[];
    __shared__ float pSq[928];
    __shared__ float sNxi[M], sNyi[NP];
    __shared__ float sXm[M], sYm[NP];

    const int b = blockIdx.x, tid = threadIdx.x;
    const int lane = tid & 31, w = tid >> 5;
    const int g = lane >> 2, q2 = lane & 3;
    const int r = w >> 1, s = w & 1;
    const int TBASE = s * 7, NT = 7 - s;

    uint32_t rawb = smem_u32(dsm);
    uint32_t sb = (rawb + 1023u) & ~1023u;
    char* sbuf = dsm + (sb - rawb);

    const int u8 = g_isU8;
    if (tid < M) {
        int pad = u8 ? (tp[b * M + tid] != 0) : (((const int*)tp)[b * M + tid] != 0);
        sXm[tid] = pad ? 1e4f : 0.f;
    }
    if (tid < NP) {
        int pad = (tid >= NIMG) ? 1
                : (u8 ? (ip[b * NIMG + tid] != 0) : (((const int*)ip)[b * NIMG + tid] != 0));
        sYm[tid] = pad ? 1e4f : 0.f;
    }

    const float* seqb = seq + (size_t)b * 228 * D;
    const int row = tid >> 2, seg = tid & 3;
    const int hasY = tid < 416;
    const float* px = seqb + (size_t)row * D + seg * 16;
    const float* py = (hasY && row < NIMG)
                    ? (seqb + (size_t)(128 + row) * D + seg * 16) : nullptr;
    const uint32_t off0 = (uint32_t)(row * 128 + seg * 32);
    const uint32_t swz0 = SWZ(off0), swz1 = SWZ(off0 + 16);

    const int j8 = lane >> 3, sub = lane & 7;
    const uint32_t arow_off = (uint32_t)((16 * r + ((j8 & 1) << 3) + sub) * 128);
    const int acol = (j8 >> 1) * 8;
    const int bcol = j8 * 8;

    float acc[28];
#pragma unroll
    for (int i = 0; i < 28; i++) acc[i] = 0.f;
    float nacc0 = 0.f, nacc1 = 0.f;

    float4 vx[4], vy[4];
    {
        const float4* p4 = (const float4*)px;
        vx[0] = p4[0]; vx[1] = p4[1]; vx[2] = p4[2]; vx[3] = p4[3];
        if (hasY) {
            if (py) { const float4* q4 = (const float4*)py;
                      vy[0] = q4[0]; vy[1] = q4[1]; vy[2] = q4[2]; vy[3] = q4[3]; }
            else vy[0] = vy[1] = vy[2] = vy[3] = make_float4(0.f, 0.f, 0.f, 0.f);
        }
    }

    for (int c = 0; c < 12; c++) {
        char* bb = sbuf + (uint32_t)(c & 1) * BUF_BYTES;
        {
            float ss = 0.f;
#pragma unroll
            for (int h = 0; h < 2; h++) {
                float4 f0 = vx[2 * h], f1 = vx[2 * h + 1];
                ss += f0.x*f0.x + f0.y*f0.y + f0.z*f0.z + f0.w*f0.w
                    + f1.x*f1.x + f1.y*f1.y + f1.z*f1.z + f1.w*f1.w;
                uint4 hi, lo;
                split2(f0.x, f0.y, hi.x, lo.x);
                split2(f0.z, f0.w, hi.y, lo.y);
                split2(f1.x, f1.y, hi.z, lo.z);
                split2(f1.z, f1.w, hi.w, lo.w);
                uint32_t sw = h ? swz1 : swz0;
                *(uint4*)(bb + XHI_OFF + sw) = hi;
                *(uint4*)(bb + XLO_OFF + sw) = lo;
            }
            nacc0 += ss;
        }
        if (hasY) {
            float ss = 0.f;
#pragma unroll
            for (int h = 0; h < 2; h++) {
                float4 f0 = vy[2 * h], f1 = vy[2 * h + 1];
                ss += f0.x*f0.x + f0.y*f0.y + f0.z*f0.z + f0.w*f0.w
                    + f1.x*f1.x + f1.y*f1.y + f1.z*f1.z + f1.w*f1.w;
                uint4 hi, lo;
                split2(f0.x, f0.y, hi.x, lo.x);
                split2(f0.z, f0.w, hi.y, lo.y);
                split2(f1.x, f1.y, hi.z, lo.z);
                split2(f1.z, f1.w, hi.w, lo.w);
                uint32_t sw = h ? swz1 : swz0;
                *(uint4*)(bb + YHI_OFF + sw) = hi;
                *(uint4*)(bb + YLO_OFF + sw) = lo;
            }
            nacc1 += ss;
        }
        __syncthreads();

        if (c < 11) {
            const float4* p4 = (const float4*)(px + (c + 1) * 64);
            vx[0] = p4[0]; vx[1] = p4[1]; vx[2] = p4[2]; vx[3] = p4[3];
            if (hasY) {
                if (py) { const float4* q4 = (const float4*)(py + (c + 1) * 64);
                          vy[0] = q4[0]; vy[1] = q4[1]; vy[2] = q4[2]; vy[3] = q4[3]; }
                else vy[0] = vy[1] = vy[2] = vy[3] = make_float4(0.f, 0.f, 0.f, 0.f);
            }
        }

        uint32_t bbase = sb + (uint32_t)(c & 1) * BUF_BYTES;
#pragma unroll
        for (int k0 = 0; k0 < 64; k0 += 32) {
            uint32_t ah0[4], ah1[4], al0[4], al1[4];
            uint32_t offA0 = SWZ(arow_off + (uint32_t)((k0 + acol) * 2));
            uint32_t offA1 = SWZ(arow_off + (uint32_t)((k0 + 16 + acol) * 2));
            ldsm4(bbase + XHI_OFF + offA0, ah0);
            ldsm4(bbase + XHI_OFF + offA1, ah1);
            ldsm4(bbase + XLO_OFF + offA0, al0);
            ldsm4(bbase + XLO_OFF + offA1, al1);
#pragma unroll
            for (int ti = 0; ti < 7; ti++) {
                if (ti < NT) {
                    int t = TBASE + ti;
                    uint32_t offB = SWZ((uint32_t)((8 * t + sub) * 128 + (k0 + bcol) * 2));
                    uint32_t bh[4], bl[4];
                    ldsm4(bbase + YHI_OFF + offB, bh);
                    ldsm4(bbase + YLO_OFF + offB, bl);
                    float* d = &acc[ti * 4];
                    mma_bf16(d, ah0, bh[0], bh[1]);
                    mma_bf16(d, al0, bh[0], bh[1]);
                    mma_bf16(d, ah0, bl[0], bl[1]);
                    mma_bf16(d, ah1, bh[2], bh[3]);
                    mma_bf16(d, al1, bh[2], bh[3]);
                    mma_bf16(d, ah1, bl[2], bl[3]);
                }
            }
        }
    }

    pSq[tid] = nacc0;
    if (hasY) pSq[512 + tid] = nacc1;
    __syncthreads();
    if (tid < M) {
        float ss = pSq[4 * tid] + pSq[4 * tid + 1] + pSq[4 * tid + 2] + pSq[4 * tid + 3];
        sNxi[tid] = 1.f / fmaxf(sqrtf(ss), 1e-5f);
    } else if (tid < M + NP) {
        int n = tid - M;
        float ss = pSq[512 + 4 * n] + pSq[512 + 4 * n + 1]
                 + pSq[512 + 4 * n + 2] + pSq[512 + 4 * n + 3];
        sNyi[n] = 1.f / fmaxf(sqrtf(ss), 1e-5f);
    }
    __syncthreads();

    // epilogue -> g_A in ipot blob order: ((b*8 + r)*13 + t)*128 + lane*4
    const int m0 = 16 * r + g, m1 = m0 + 8;
    const float xm0 = sXm[m0], xm1 = sXm[m1];
    const float nx0 = sNxi[m0], nx1 = sNxi[m1];
    float* gAout = g_A + (((size_t)b * 8 + r) * 13 + TBASE) * 128;
#pragma unroll
    for (int ti = 0; ti < 7; ti++) {
        if (ti < NT) {
            int t = TBASE + ti;
            int n0 = 8 * t + 2 * q2, n1 = n0 + 1;
            float ny0 = sNyi[n0], ny1 = sNyi[n1];
            float ym0 = sYm[n0],  ym1 = sYm[n1];
            float4 a;
            a.x = (xm0 > 0.f || ym0 > 0.f) ? 0.f
                : __expf(2.f * (acc[ti * 4 + 0] * nx0 * ny0 - 1.f));
            a.y = (xm0 > 0.f || ym1 > 0.f) ? 0.f
                : __expf(2.f * (acc[ti * 4 + 1] * nx0 * ny1 - 1.f));
            a.z = (xm1 > 0.f || ym0 > 0.f) ? 0.f
                : __expf(2.f * (acc[ti * 4 + 2] * nx1 * ny0 - 1.f));
            a.w = (xm1 > 0.f || ym1 > 0.f) ? 0.f
                : __expf(2.f * (acc[ti * 4 + 3] * nx1 * ny1 - 1.f));
            *(float4*)(gAout + ti * 128 + lane * 4) = a;
        }
    }
}

// ---------------------------------------------------------------------------
// IPOT kernel: 256 threads (8 warps), 2 CTAs/SM. A in 53KB dynamic smem
// (fragment blob, conflict-free LDS.128), Q register-resident (52/thread).
// Warp w owns m-rows 16w..16w+15 and ALL 13 n-tiles -> sigma is warp-local;
// 2 barriers per iteration.
// ---------------------------------------------------------------------------
__global__ void __launch_bounds__(256, 2) k_ipot(const unsigned char* __restrict__ tp,
                                                 const unsigned char* __restrict__ ip) {
    extern __shared__ __align__(16) float sA[];   // NP*M floats
    __shared__ float sXm[M], sYm[NP];
    __shared__ __align__(8) float sDelta[NP];
    __shared__ __align__(8) float sQsPart[8 * NP];
    __shared__ float sRed[8];
    __shared__ int sCx, sCy;

    const int b = blockIdx.x, tid = threadIdx.x;
    const int lane = tid & 31, w = tid >> 5;
    const int g = lane >> 2, q2 = lane & 3;

    if (tid == 0) { sCx = 0; sCy = 0; }
    __syncthreads();
    const int u8 = g_isU8;
    if (tid < M) {
        int pad = u8 ? (tp[b * M + tid] != 0) : (((const int*)tp)[b * M + tid] != 0);
        sXm[tid] = pad ? 1e4f : 0.f;
        if (pad) atomicAdd(&sCx, 1);
    }
    if (tid < NP) {
        int pad = (tid >= NIMG) ? 1
                : (u8 ? (ip[b * NIMG + tid] != 0) : (((const int*)ip)[b * NIMG + tid] != 0));
        sYm[tid] = pad ? 1e4f : 0.f;
        if (pad && tid < NIMG) atomicAdd(&sCy, 1);
    }

    // A blob gmem -> smem (coalesced both ends)
    const float4* gA4 = (const float4*)(g_A + (size_t)b * (NP * M));
    float4* sA4 = (float4*)sA;
#pragma unroll
    for (int k = 0; k < 13; k++) sA4[k * 256 + tid] = gA4[k * 256 + tid];
    __syncthreads();

    // Q init = A (register-resident)
    const float4* myA = sA4 + w * 13 * 32 + lane;
    float Qr[52];
#pragma unroll
    for (int t = 0; t < 13; t++) {
        float4 a = myA[t * 32];
        Qr[t * 4 + 0] = a.x; Qr[t * 4 + 1] = a.y;
        Qr[t * 4 + 2] = a.z; Qr[t * 4 + 3] = a.w;
    }

    const int m0 = 16 * w + g, m1 = m0 + 8;
    const float xm0 = sXm[m0], xm1 = sXm[m1];
    const float xl = (float)(M - sCx), yl = (float)(NIMG - sCy);

    float sig0 = xm0 > 0.f ? 0.f : 1.f / xl;
    float sig1 = xm1 > 0.f ? 0.f : 1.f / xl;

    // initial qs partials
#pragma unroll
    for (int t = 0; t < 13; t++) {
        float qp0 = Qr[t * 4 + 0] * sig0 + Qr[t * 4 + 2] * sig1;
        float qp1 = Qr[t * 4 + 1] * sig0 + Qr[t * 4 + 3] * sig1;
        qp0 += __shfl_xor_sync(0xffffffffu, qp0, 4);
        qp0 += __shfl_xor_sync(0xffffffffu, qp0, 8);
        qp0 += __shfl_xor_sync(0xffffffffu, qp0, 16);
        qp1 += __shfl_xor_sync(0xffffffffu, qp1, 4);
        qp1 += __shfl_xor_sync(0xffffffffu, qp1, 8);
        qp1 += __shfl_xor_sync(0xffffffffu, qp1, 16);
        if (g == (t & 7))
            *(float2*)&sQsPart[w * NP + 8 * t + 2 * q2] = make_float2(qp0, qp1);
    }
    __syncthreads();

    float ot = 0.f;
#pragma unroll 1
    for (int it = 0; it < ITERS; it++) {
        if (tid < NP) {
            float qs = 0.f;
#pragma unroll
            for (int ww = 0; ww < 8; ww++) qs += sQsPart[ww * NP + tid];
            sDelta[tid] = __fdividef(1.f, yl * qs + sYm[tid]);
        }
        __syncthreads();

        // r[m] = sum_n delta[n]*Q[n,m] -> warp-local sigma (xor 1,2)
        float2 dl[13];
        float p0 = 0.f, p1 = 0.f;
#pragma unroll
        for (int t = 0; t < 13; t++) {
            dl[t] = *(const float2*)&sDelta[8 * t + 2 * q2];
            p0 += dl[t].x * Qr[t * 4 + 0] + dl[t].y * Qr[t * 4 + 1];
            p1 += dl[t].x * Qr[t * 4 + 2] + dl[t].y * Qr[t * 4 + 3];
        }
        p0 += __shfl_xor_sync(0xffffffffu, p0, 1);
        p0 += __shfl_xor_sync(0xffffffffu, p0, 2);
        p1 += __shfl_xor_sync(0xffffffffu, p1, 1);
        p1 += __shfl_xor_sync(0xffffffffu, p1, 2);
        sig0 = __fdividef(1.f, xl * p0 + xm0);
        sig1 = __fdividef(1.f, xl * p1 + xm1);

        if (it < ITERS - 1) {
#pragma unroll
            for (int t = 0; t < 13; t++) {
                float4 a = myA[t * 32];
                float ds00 = dl[t].x * sig0, ds01 = dl[t].y * sig0;
                float ds10 = dl[t].x * sig1, ds11 = dl[t].y * sig1;
                float q0 = a.x * Qr[t * 4 + 0] * ds00;
                float q1 = a.y * Qr[t * 4 + 1] * ds01;
                float q2v = a.z * Qr[t * 4 + 2] * ds10;
                float q3 = a.w * Qr[t * 4 + 3] * ds11;
                Qr[t * 4 + 0] = q0; Qr[t * 4 + 1] = q1;
                Qr[t * 4 + 2] = q2v; Qr[t * 4 + 3] = q3;
                float qp0 = q0 * sig0 + q2v * sig1;
                float qp1 = q1 * sig0 + q3 * sig1;
                qp0 += __shfl_xor_sync(0xffffffffu, qp0, 4);
                qp0 += __shfl_xor_sync(0xffffffffu, qp0, 8);
                qp0 += __shfl_xor_sync(0xffffffffu, qp0, 16);
                qp1 += __shfl_xor_sync(0xffffffffu, qp1, 4);
                qp1 += __shfl_xor_sync(0xffffffffu, qp1, 8);
                qp1 += __shfl_xor_sync(0xffffffffu, qp1, 16);
                if (g == (t & 7))
                    *(float2*)&sQsPart[w * NP + 8 * t + 2 * q2] = make_float2(qp0, qp1);
            }
        } else {
#pragma unroll
            for (int t = 0; t < 13; t++) {
                float4 a = myA[t * 32];
                if (a.x > 0.f) ot += (-0.5f * __logf(a.x)) * Qr[t * 4 + 0] * dl[t].x * sig0;
                if (a.y > 0.f) ot += (-0.5f * __logf(a.y)) * Qr[t * 4 + 1] * dl[t].y * sig0;
                if (a.z > 0.f) ot += (-0.5f * __logf(a.z)) * Qr[t * 4 + 2] * dl[t].x * sig1;
                if (a.w > 0.f) ot += (-0.5f * __logf(a.w)) * Qr[t * 4 + 3] * dl[t].y * sig1;
            }
        }
        __syncthreads();
    }

    ot += __shfl_xor_sync(0xffffffffu, ot, 16);
    ot += __shfl_xor_sync(0xffffffffu, ot, 8);
    ot += __shfl_xor_sync(0xffffffffu, ot, 4);
    ot += __shfl_xor_sync(0xffffffffu, ot, 2);
    ot += __shfl_xor_sync(0xffffffffu, ot, 1);
    if (lane == 0) sRed[w] = ot;
    __syncthreads();
    if (tid == 0) {
        float sum = 0.f;
#pragma unroll
        for (int ww = 0; ww < 8; ww++) sum += sRed[ww];
        g_ot[b] = sum;
    }
}

// ---------------------------------------------------------------------------
// Final signed batch reduction -> scalar loss.
// ---------------------------------------------------------------------------
__global__ void k_final(const int* __restrict__ isc, float* __restrict__ out) {
    int t = threadIdx.x;
    __shared__ float sRed[8];
    float v = g_ot[t];
    float s = (isc[t] == 1) ? v : -v;
    s += __shfl_xor_sync(0xffffffffu, s, 16);
    s += __shfl_xor_sync(0xffffffffu, s, 8);
    s += __shfl_xor_sync(0xffffffffu, s, 4);
    s += __shfl_xor_sync(0xffffffffu, s, 2);
    s += __shfl_xor_sync(0xffffffffu, s, 1);
    if ((t & 31) == 0) sRed[t >> 5] = s;
    __syncthreads();
    if (t == 0) {
        float tot = 0.f;
#pragma unroll
        for (int w = 0; w < 8; w++) tot += sRed[w];
        out[0] = tot / (float)BATCH;
    }
}

// ---------------------------------------------------------------------------
extern "C" void kernel_launch(void* const* d_in, const int* in_sizes, int n_in,
                              void* d_out, int out_size) {
    const float* seq = (const float*)d_in[0];
    const unsigned char* tp = (const unsigned char*)d_in[3];
    const unsigned char* ip = (const unsigned char*)d_in[4];
    const int* isc = (const int*)d_in[5];
    float* out = (float*)d_out;

    cudaFuncSetAttribute(k_gemm, cudaFuncAttributeMaxDynamicSharedMemorySize,
                         DSM_GEMM);
    cudaFuncSetAttribute(k_ipot, cudaFuncAttributeMaxDynamicSharedMemorySize,
                         DSM_IPOT);

    k_detect<<<1, 512>>>(tp, ip);
    k_nop<<<1, 32>>>();   // spacer: k_ipot is profiled launch #4
    k_gemm<<<BATCH, GTHREADS, DSM_GEMM>>>(seq, tp, ip);
    k_ipot<<<BATCH, 256, DSM_IPOT>>>(tp, ip);
    k_final<<<1, 256>>>(isc, out);
}

// round 8
// speedup vs baseline: 1.2475x; 1.1374x over previous
#include <cuda_runtime.h>
#include <cuda_bf16.h>
#include <stdint.h>

// Problem constants
#define BATCH 256
#define M 128
#define NIMG 100
#define NP 104          // 13 * 8
#define D 768
#define ITERS 50
#define GTHREADS 512

// Staging layout (per buffer, swizzled bf16, 128B rows)
#define XHI_OFF 0u
#define XLO_OFF 16384u
#define YHI_OFF 32768u
#define YLO_OFF 46080u
#define BUF_BYTES 59392u
#define DSM_GEMM (2 * 59392 + 1024)
#define DSM_IPOT (NP * M * 4)     // 53248: A matrix blob

#define QP_STRIDE 68              // 64 partial cols + 4 pad floats

#define SWZ(o) ((o) ^ (((o) >> 3) & 0x70))

// A stored as fragment blob in ipot geometry:
// g_A[((b*8 + r)*13 + t)*128 + lane*4 + e]
__device__ __align__(16) float g_A[BATCH * 8 * 13 * 128];
__device__ float g_ot[BATCH];
__device__ int   g_isU8;

// ---------------------------------------------------------------------------
// Helpers
// ---------------------------------------------------------------------------
__device__ __forceinline__ uint32_t smem_u32(const void* p) {
    uint32_t a;
    asm("{ .reg .u64 t; cvta.to.shared.u64 t, %1; cvt.u32.u64 %0, t; }"
        : "=r"(a) : "l"(p));
    return a;
}
__device__ __forceinline__ void ldsm4(uint32_t addr, uint32_t* r) {
    asm volatile("ldmatrix.sync.aligned.m8n8.x4.shared.b16 {%0,%1,%2,%3}, [%4];"
                 : "=r"(r[0]), "=r"(r[1]), "=r"(r[2]), "=r"(r[3]) : "r"(addr));
}
__device__ __forceinline__ void mma_bf16(float* d, const uint32_t* a,
                                         uint32_t b0, uint32_t b1) {
    asm volatile(
        "mma.sync.aligned.m16n8k16.row.col.f32.bf16.bf16.f32 "
        "{%0,%1,%2,%3},{%4,%5,%6,%7},{%8,%9},{%0,%1,%2,%3};"
        : "+f"(d[0]), "+f"(d[1]), "+f"(d[2]), "+f"(d[3])
        : "r"(a[0]), "r"(a[1]), "r"(a[2]), "r"(a[3]), "r"(b0), "r"(b1));
}
__device__ __forceinline__ void split2(float a, float b, uint32_t& hi, uint32_t& lo) {
    asm("cvt.rn.bf16x2.f32 %0, %1, %2;" : "=r"(hi) : "f"(b), "f"(a));
    float ah = __uint_as_float(hi << 16);
    float bh = __uint_as_float(hi & 0xffff0000u);
    float la = a - ah, lb = b - bh;
    asm("cvt.rn.bf16x2.f32 %0, %1, %2;" : "=r"(lo) : "f"(lb), "f"(la));
}

__global__ void k_nop() {}

// ---------------------------------------------------------------------------
// Pad-dtype detect (uint8-bool vs int32)
// ---------------------------------------------------------------------------
__global__ void __launch_bounds__(512) k_detect(const unsigned char* __restrict__ tp,
                                                const unsigned char* __restrict__ ip) {
    __shared__ int sflag;
    int tid = threadIdx.x;
    if (tid == 0) sflag = 0;
    __syncthreads();
    uint32_t acc = 0;
    const uint4* t4 = (const uint4*)tp;
    for (int i = tid; i < 2048; i += 512) {
        uint4 v = t4[i];
        acc |= (v.x | v.y | v.z | v.w) & 0xFFFFFF00u;
    }
    const uint4* i4 = (const uint4*)ip;
    for (int i = tid; i < 1600; i += 512) {
        uint4 v = i4[i];
        acc |= (v.x | v.y | v.z | v.w) & 0xFFFFFF00u;
    }
    uint32_t any = __ballot_sync(0xffffffffu, acc != 0);
    if ((tid & 31) == 0 && any) atomicOr(&sflag, 1);
    __syncthreads();
    if (tid == 0) g_isU8 = sflag;
}

// ---------------------------------------------------------------------------
// GEMM kernel (unchanged): split-bf16 mma.sync, double-buffered staging;
// epilogue writes A to g_A in ipot fragment-blob order.
// ---------------------------------------------------------------------------
__global__ void __launch_bounds__(GTHREADS) k_gemm(const float* __restrict__ seq,
                                                   const unsigned char* __restrict__ tp,
                                                   const unsigned char* __restrict__ ip) {
    extern __shared__ __align__(16) char dsm[];
    __shared__ float pSq[928];
    __shared__ float sNxi[M], sNyi[NP];
    __shared__ float sXm[M], sYm[NP];

    const int b = blockIdx.x, tid = threadIdx.x;
    const int lane = tid & 31, w = tid >> 5;
    const int g = lane >> 2, q2 = lane & 3;
    const int r = w >> 1, s = w & 1;
    const int TBASE = s * 7, NT = 7 - s;

    uint32_t rawb = smem_u32(dsm);
    uint32_t sb = (rawb + 1023u) & ~1023u;
    char* sbuf = dsm + (sb - rawb);

    const int u8 = g_isU8;
    if (tid < M) {
        int pad = u8 ? (tp[b * M + tid] != 0) : (((const int*)tp)[b * M + tid] != 0);
        sXm[tid] = pad ? 1e4f : 0.f;
    }
    if (tid < NP) {
        int pad = (tid >= NIMG) ? 1
                : (u8 ? (ip[b * NIMG + tid] != 0) : (((const int*)ip)[b * NIMG + tid] != 0));
        sYm[tid] = pad ? 1e4f : 0.f;
    }

    const float* seqb = seq + (size_t)b * 228 * D;
    const int row = tid >> 2, seg = tid & 3;
    const int hasY = tid < 416;
    const float* px = seqb + (size_t)row * D + seg * 16;
    const float* py = (hasY && row < NIMG)
                    ? (seqb + (size_t)(128 + row) * D + seg * 16) : nullptr;
    const uint32_t off0 = (uint32_t)(row * 128 + seg * 32);
    const uint32_t swz0 = SWZ(off0), swz1 = SWZ(off0 + 16);

    const int j8 = lane >> 3, sub = lane & 7;
    const uint32_t arow_off = (uint32_t)((16 * r + ((j8 & 1) << 3) + sub) * 128);
    const int acol = (j8 >> 1) * 8;
    const int bcol = j8 * 8;

    float acc[28];
#pragma unroll
    for (int i = 0; i < 28; i++) acc[i] = 0.f;
    float nacc0 = 0.f, nacc1 = 0.f;

    float4 vx[4], vy[4];
    {
        const float4* p4 = (const float4*)px;
        vx[0] = p4[0]; vx[1] = p4[1]; vx[2] = p4[2]; vx[3] = p4[3];
        if (hasY) {
            if (py) { const float4* q4 = (const float4*)py;
                      vy[0] = q4[0]; vy[1] = q4[1]; vy[2] = q4[2]; vy[3] = q4[3]; }
            else vy[0] = vy[1] = vy[2] = vy[3] = make_float4(0.f, 0.f, 0.f, 0.f);
        }
    }

    for (int c = 0; c < 12; c++) {
        char* bb = sbuf + (uint32_t)(c & 1) * BUF_BYTES;
        {
            float ss = 0.f;
#pragma unroll
            for (int h = 0; h < 2; h++) {
                float4 f0 = vx[2 * h], f1 = vx[2 * h + 1];
                ss += f0.x*f0.x + f0.y*f0.y + f0.z*f0.z + f0.w*f0.w
                    + f1.x*f1.x + f1.y*f1.y + f1.z*f1.z + f1.w*f1.w;
                uint4 hi, lo;
                split2(f0.x, f0.y, hi.x, lo.x);
                split2(f0.z, f0.w, hi.y, lo.y);
                split2(f1.x, f1.y, hi.z, lo.z);
                split2(f1.z, f1.w, hi.w, lo.w);
                uint32_t sw = h ? swz1 : swz0;
                *(uint4*)(bb + XHI_OFF + sw) = hi;
                *(uint4*)(bb + XLO_OFF + sw) = lo;
            }
            nacc0 += ss;
        }
        if (hasY) {
            float ss = 0.f;
#pragma unroll
            for (int h = 0; h < 2; h++) {
                float4 f0 = vy[2 * h], f1 = vy[2 * h + 1];
                ss += f0.x*f0.x + f0.y*f0.y + f0.z*f0.z + f0.w*f0.w
                    + f1.x*f1.x + f1.y*f1.y + f1.z*f1.z + f1.w*f1.w;
                uint4 hi, lo;
                split2(f0.x, f0.y, hi.x, lo.x);
                split2(f0.z, f0.w, hi.y, lo.y);
                split2(f1.x, f1.y, hi.z, lo.z);
                split2(f1.z, f1.w, hi.w, lo.w);
                uint32_t sw = h ? swz1 : swz0;
                *(uint4*)(bb + YHI_OFF + sw) = hi;
                *(uint4*)(bb + YLO_OFF + sw) = lo;
            }
            nacc1 += ss;
        }
        __syncthreads();

        if (c < 11) {
            const float4* p4 = (const float4*)(px + (c + 1) * 64);
            vx[0] = p4[0]; vx[1] = p4[1]; vx[2] = p4[2]; vx[3] = p4[3];
            if (hasY) {
                if (py) { const float4* q4 = (const float4*)(py + (c + 1) * 64);
                          vy[0] = q4[0]; vy[1] = q4[1]; vy[2] = q4[2]; vy[3] = q4[3]; }
                else vy[0] = vy[1] = vy[2] = vy[3] = make_float4(0.f, 0.f, 0.f, 0.f);
            }
        }

        uint32_t bbase = sb + (uint32_t)(c & 1) * BUF_BYTES;
#pragma unroll
        for (int k0 = 0; k0 < 64; k0 += 32) {
            uint32_t ah0[4], ah1[4], al0[4], al1[4];
            uint32_t offA0 = SWZ(arow_off + (uint32_t)((k0 + acol) * 2));
            uint32_t offA1 = SWZ(arow_off + (uint32_t)((k0 + 16 + acol) * 2));
            ldsm4(bbase + XHI_OFF + offA0, ah0);
            ldsm4(bbase + XHI_OFF + offA1, ah1);
            ldsm4(bbase + XLO_OFF + offA0, al0);
            ldsm4(bbase + XLO_OFF + offA1, al1);
#pragma unroll
            for (int ti = 0; ti < 7; ti++) {
                if (ti < NT) {
                    int t = TBASE + ti;
                    uint32_t offB = SWZ((uint32_t)((8 * t + sub) * 128 + (k0 + bcol) * 2));
                    uint32_t bh[4], bl[4];
                    ldsm4(bbase + YHI_OFF + offB, bh);
                    ldsm4(bbase + YLO_OFF + offB, bl);
                    float* d = &acc[ti * 4];
                    mma_bf16(d, ah0, bh[0], bh[1]);
                    mma_bf16(d, al0, bh[0], bh[1]);
                    mma_bf16(d, ah0, bl[0], bl[1]);
                    mma_bf16(d, ah1, bh[2], bh[3]);
                    mma_bf16(d, al1, bh[2], bh[3]);
                    mma_bf16(d, ah1, bl[2], bl[3]);
                }
            }
        }
    }

    pSq[tid] = nacc0;
    if (hasY) pSq[512 + tid] = nacc1;
    __syncthreads();
    if (tid < M) {
        float ss = pSq[4 * tid] + pSq[4 * tid + 1] + pSq[4 * tid + 2] + pSq[4 * tid + 3];
        sNxi[tid] = 1.f / fmaxf(sqrtf(ss), 1e-5f);
    } else if (tid < M + NP) {
        int n = tid - M;
        float ss = pSq[512 + 4 * n] + pSq[512 + 4 * n + 1]
                 + pSq[512 + 4 * n + 2] + pSq[512 + 4 * n + 3];
        sNyi[n] = 1.f / fmaxf(sqrtf(ss), 1e-5f);
    }
    __syncthreads();

    const int m0 = 16 * r + g, m1 = m0 + 8;
    const float xm0 = sXm[m0], xm1 = sXm[m1];
    const float nx0 = sNxi[m0], nx1 = sNxi[m1];
    float* gAout = g_A + (((size_t)b * 8 + r) * 13 + TBASE) * 128;
#pragma unroll
    for (int ti = 0; ti < 7; ti++) {
        if (ti < NT) {
            int t = TBASE + ti;
            int n0 = 8 * t + 2 * q2, n1 = n0 + 1;
            float ny0 = sNyi[n0], ny1 = sNyi[n1];
            float ym0 = sYm[n0],  ym1 = sYm[n1];
            float4 a;
            a.x = (xm0 > 0.f || ym0 > 0.f) ? 0.f
                : __expf(2.f * (acc[ti * 4 + 0] * nx0 * ny0 - 1.f));
            a.y = (xm0 > 0.f || ym1 > 0.f) ? 0.f
                : __expf(2.f * (acc[ti * 4 + 1] * nx0 * ny1 - 1.f));
            a.z = (xm1 > 0.f || ym0 > 0.f) ? 0.f
                : __expf(2.f * (acc[ti * 4 + 2] * nx1 * ny0 - 1.f));
            a.w = (xm1 > 0.f || ym1 > 0.f) ? 0.f
                : __expf(2.f * (acc[ti * 4 + 3] * nx1 * ny1 - 1.f));
            *(float4*)(gAout + ti * 128 + lane * 4) = a;
        }
    }
}

// ---------------------------------------------------------------------------
// IPOT kernel: 256 threads (8 warps), 2 CTAs/SM. A in 53KB dynamic smem,
// Q register-resident. qs reduction: NO shuffles — raw per-(warp,g) partials
// stored to sQP[n][64] (stride 68, conflict-free STS.32), summed by the 104
// delta threads with 16 LDS.128 each.
// ---------------------------------------------------------------------------
__global__ void __launch_bounds__(256, 2) k_ipot(const unsigned char* __restrict__ tp,
                                                 const unsigned char* __restrict__ ip) {
    extern __shared__ __align__(16) float sA[];   // NP*M floats
    __shared__ __align__(16) float sQP[NP * QP_STRIDE];
    __shared__ float sXm[M], sYm[NP];
    __shared__ __align__(8) float sDelta[NP];
    __shared__ float sRed[8];
    __shared__ int sCx, sCy;

    const int b = blockIdx.x, tid = threadIdx.x;
    const int lane = tid & 31, w = tid >> 5;
    const int g = lane >> 2, q2 = lane & 3;
    const int col = 8 * w + g;            // partial column 0..63

    if (tid == 0) { sCx = 0; sCy = 0; }
    __syncthreads();
    const int u8 = g_isU8;
    if (tid < M) {
        int pad = u8 ? (tp[b * M + tid] != 0) : (((const int*)tp)[b * M + tid] != 0);
        sXm[tid] = pad ? 1e4f : 0.f;
        if (pad) atomicAdd(&sCx, 1);
    }
    if (tid < NP) {
        int pad = (tid >= NIMG) ? 1
                : (u8 ? (ip[b * NIMG + tid] != 0) : (((const int*)ip)[b * NIMG + tid] != 0));
        sYm[tid] = pad ? 1e4f : 0.f;
        if (pad && tid < NIMG) atomicAdd(&sCy, 1);
    }

    // A blob gmem -> smem (coalesced both ends)
    const float4* gA4 = (const float4*)(g_A + (size_t)b * (NP * M));
    float4* sA4 = (float4*)sA;
#pragma unroll
    for (int k = 0; k < 13; k++) sA4[k * 256 + tid] = gA4[k * 256 + tid];
    __syncthreads();

    // Q init = A (register-resident)
    const float4* myA = sA4 + w * 13 * 32 + lane;
    float Qr[52];
#pragma unroll
    for (int t = 0; t < 13; t++) {
        float4 a = myA[t * 32];
        Qr[t * 4 + 0] = a.x; Qr[t * 4 + 1] = a.y;
        Qr[t * 4 + 2] = a.z; Qr[t * 4 + 3] = a.w;
    }

    const int m0 = 16 * w + g, m1 = m0 + 8;
    const float xm0 = sXm[m0], xm1 = sXm[m1];
    const float xl = (float)(M - sCx), yl = (float)(NIMG - sCy);

    float sig0 = xm0 > 0.f ? 0.f : 1.f / xl;
    float sig1 = xm1 > 0.f ? 0.f : 1.f / xl;

    // initial qs partials -> sQP (no shuffles)
#pragma unroll
    for (int t = 0; t < 13; t++) {
        int n0 = 8 * t + 2 * q2;
        sQP[n0 * QP_STRIDE + col]       = Qr[t * 4 + 0] * sig0 + Qr[t * 4 + 2] * sig1;
        sQP[(n0 + 1) * QP_STRIDE + col] = Qr[t * 4 + 1] * sig0 + Qr[t * 4 + 3] * sig1;
    }
    __syncthreads();

    float ot = 0.f;
#pragma unroll 1
    for (int it = 0; it < ITERS; it++) {
        // delta[n]: sum 64 partials (16 LDS.128, 4 accumulators)
        if (tid < NP) {
            const float4* rp = (const float4*)&sQP[tid * QP_STRIDE];
            float4 r0 = rp[0], r1 = rp[1], r2 = rp[2], r3 = rp[3];
#pragma unroll
            for (int j = 4; j < 16; j += 4) {
                float4 v0 = rp[j], v1 = rp[j + 1], v2 = rp[j + 2], v3 = rp[j + 3];
                r0.x += v0.x; r0.y += v0.y; r0.z += v0.z; r0.w += v0.w;
                r1.x += v1.x; r1.y += v1.y; r1.z += v1.z; r1.w += v1.w;
                r2.x += v2.x; r2.y += v2.y; r2.z += v2.z; r2.w += v2.w;
                r3.x += v3.x; r3.y += v3.y; r3.z += v3.z; r3.w += v3.w;
            }
            float qs = (r0.x + r0.y + r0.z + r0.w) + (r1.x + r1.y + r1.z + r1.w)
                     + (r2.x + r2.y + r2.z + r2.w) + (r3.x + r3.y + r3.z + r3.w);
            sDelta[tid] = __fdividef(1.f, yl * qs + sYm[tid]);
        }
        __syncthreads();

        // r[m] = sum_n delta[n]*Q[n,m] -> warp-local sigma (xor 1,2)
        float2 dl[13];
        float p0 = 0.f, p1 = 0.f;
#pragma unroll
        for (int t = 0; t < 13; t++) {
            dl[t] = *(const float2*)&sDelta[8 * t + 2 * q2];
            p0 += dl[t].x * Qr[t * 4 + 0] + dl[t].y * Qr[t * 4 + 1];
            p1 += dl[t].x * Qr[t * 4 + 2] + dl[t].y * Qr[t * 4 + 3];
        }
        p0 += __shfl_xor_sync(0xffffffffu, p0, 1);
        p0 += __shfl_xor_sync(0xffffffffu, p0, 2);
        p1 += __shfl_xor_sync(0xffffffffu, p1, 1);
        p1 += __shfl_xor_sync(0xffffffffu, p1, 2);
        sig0 = __fdividef(1.f, xl * p0 + xm0);
        sig1 = __fdividef(1.f, xl * p1 + xm1);

        if (it < ITERS - 1) {
#pragma unroll
            for (int t = 0; t < 13; t++) {
                float4 a = myA[t * 32];
                float ds00 = dl[t].x * sig0, ds01 = dl[t].y * sig0;
                float ds10 = dl[t].x * sig1, ds11 = dl[t].y * sig1;
                float q0 = a.x * Qr[t * 4 + 0] * ds00;
                float q1 = a.y * Qr[t * 4 + 1] * ds01;
                float q2v = a.z * Qr[t * 4 + 2] * ds10;
                float q3 = a.w * Qr[t * 4 + 3] * ds11;
                Qr[t * 4 + 0] = q0; Qr[t * 4 + 1] = q1;
                Qr[t * 4 + 2] = q2v; Qr[t * 4 + 3] = q3;
                int n0 = 8 * t + 2 * q2;
                sQP[n0 * QP_STRIDE + col]       = q0 * sig0 + q2v * sig1;
                sQP[(n0 + 1) * QP_STRIDE + col] = q1 * sig0 + q3 * sig1;
            }
        } else {
#pragma unroll
            for (int t = 0; t < 13; t++) {
                float4 a = myA[t * 32];
                if (a.x > 0.f) ot += (-0.5f * __logf(a.x)) * Qr[t * 4 + 0] * dl[t].x * sig0;
                if (a.y > 0.f) ot += (-0.5f * __logf(a.y)) * Qr[t * 4 + 1] * dl[t].y * sig0;
                if (a.z > 0.f) ot += (-0.5f * __logf(a.z)) * Qr[t * 4 + 2] * dl[t].x * sig1;
                if (a.w > 0.f) ot += (-0.5f * __logf(a.w)) * Qr[t * 4 + 3] * dl[t].y * sig1;
            }
        }
        __syncthreads();
    }

    ot += __shfl_xor_sync(0xffffffffu, ot, 16);
    ot += __shfl_xor_sync(0xffffffffu, ot, 8);
    ot += __shfl_xor_sync(0xffffffffu, ot, 4);
    ot += __shfl_xor_sync(0xffffffffu, ot, 2);
    ot += __shfl_xor_sync(0xffffffffu, ot, 1);
    if (lane == 0) sRed[w] = ot;
    __syncthreads();
    if (tid == 0) {
        float sum = 0.f;
#pragma unroll
        for (int ww = 0; ww < 8; ww++) sum += sRed[ww];
        g_ot[b] = sum;
    }
}

// ---------------------------------------------------------------------------
// Final signed batch reduction -> scalar loss.
// ---------------------------------------------------------------------------
__global__ void k_final(const int* __restrict__ isc, float* __restrict__ out) {
    int t = threadIdx.x;
    __shared__ float sRed[8];
    float v = g_ot[t];
    float s = (isc[t] == 1) ? v : -v;
    s += __shfl_xor_sync(0xffffffffu, s, 16);
    s += __shfl_xor_sync(0xffffffffu, s, 8);
    s += __shfl_xor_sync(0xffffffffu, s, 4);
    s += __shfl_xor_sync(0xffffffffu, s, 2);
    s += __shfl_xor_sync(0xffffffffu, s, 1);
    if ((t & 31) == 0) sRed[t >> 5] = s;
    __syncthreads();
    if (t == 0) {
        float tot = 0.f;
#pragma unroll
        for (int w = 0; w < 8; w++) tot += sRed[w];
        out[0] = tot / (float)BATCH;
    }
}

// ---------------------------------------------------------------------------
extern "C" void kernel_launch(void* const* d_in, const int* in_sizes, int n_in,
                              void* d_out, int out_size) {
    const float* seq = (const float*)d_in[0];
    const unsigned char* tp = (const unsigned char*)d_in[3];
    const unsigned char* ip = (const unsigned char*)d_in[4];
    const int* isc = (const int*)d_in[5];
    float* out = (float*)d_out;

    cudaFuncSetAttribute(k_gemm, cudaFuncAttributeMaxDynamicSharedMemorySize,
                         DSM_GEMM);
    cudaFuncSetAttribute(k_ipot, cudaFuncAttributeMaxDynamicSharedMemorySize,
                         DSM_IPOT);

    k_detect<<<1, 512>>>(tp, ip);
    k_nop<<<1, 32>>>();   // spacer: k_ipot is profiled launch #4
    k_gemm<<<BATCH, GTHREADS, DSM_GEMM>>>(seq, tp, ip);
    k_ipot<<<BATCH, 256, DSM_IPOT>>>(tp, ip);
    k_final<<<1, 256>>>(isc, out);
}

// round 9
// speedup vs baseline: 1.2907x; 1.0346x over previous
#include <cuda_runtime.h>
#include <cuda_bf16.h>
#include <stdint.h>

// Problem constants
#define BATCH 256
#define M 128
#define NIMG 100
#define NP 104          // 13 * 8
#define D 768
#define ITERS 50

// Half-batch GEMM staging (per buffer, swizzled bf16, 128B rows)
// X: 64 rows (half of M), Y: 104 rows (full)
#define XHI_OFF 0u
#define XLO_OFF 8192u
#define YHI_OFF 16384u
#define YLO_OFF 29696u
#define BUF_BYTES 43008u
#define DSM_GEMM (2 * 43008 + 1024)
#define DSM_IPOT (NP * M * 4)     // 53248: A matrix blob

#define QP_STRIDE 68              // 64 partial cols + 4 pad floats

#define SWZ(o) ((o) ^ (((o) >> 3) & 0x70))

// A stored as fragment blob in ipot geometry:
// g_A[((b*8 + rg)*13 + t)*128 + lane*4 + e], rg = m-row-group 0..7
__device__ __align__(16) float g_A[BATCH * 8 * 13 * 128];
__device__ float g_ot[BATCH];
__device__ int   g_isU8;

// ---------------------------------------------------------------------------
// Helpers
// ---------------------------------------------------------------------------
__device__ __forceinline__ uint32_t smem_u32(const void* p) {
    uint32_t a;
    asm("{ .reg .u64 t; cvta.to.shared.u64 t, %1; cvt.u32.u64 %0, t; }"
        : "=r"(a) : "l"(p));
    return a;
}
__device__ __forceinline__ void ldsm4(uint32_t addr, uint32_t* r) {
    asm volatile("ldmatrix.sync.aligned.m8n8.x4.shared.b16 {%0,%1,%2,%3}, [%4];"
                 : "=r"(r[0]), "=r"(r[1]), "=r"(r[2]), "=r"(r[3]) : "r"(addr));
}
__device__ __forceinline__ void mma_bf16(float* d, const uint32_t* a,
                                         uint32_t b0, uint32_t b1) {
    asm volatile(
        "mma.sync.aligned.m16n8k16.row.col.f32.bf16.bf16.f32 "
        "{%0,%1,%2,%3},{%4,%5,%6,%7},{%8,%9},{%0,%1,%2,%3};"
        : "+f"(d[0]), "+f"(d[1]), "+f"(d[2]), "+f"(d[3])
        : "r"(a[0]), "r"(a[1]), "r"(a[2]), "r"(a[3]), "r"(b0), "r"(b1));
}
__device__ __forceinline__ void split2(float a, float b, uint32_t& hi, uint32_t& lo) {
    asm("cvt.rn.bf16x2.f32 %0, %1, %2;" : "=r"(hi) : "f"(b), "f"(a));
    float ah = __uint_as_float(hi << 16);
    float bh = __uint_as_float(hi & 0xffff0000u);
    float la = a - ah, lb = b - bh;
    asm("cvt.rn.bf16x2.f32 %0, %1, %2;" : "=r"(lo) : "f"(lb), "f"(la));
}

__global__ void k_nop() {}

// ---------------------------------------------------------------------------
// Pad-dtype detect (uint8-bool vs int32)
// ---------------------------------------------------------------------------
__global__ void __launch_bounds__(512) k_detect(const unsigned char* __restrict__ tp,
                                                const unsigned char* __restrict__ ip) {
    __shared__ int sflag;
    int tid = threadIdx.x;
    if (tid == 0) sflag = 0;
    __syncthreads();
    uint32_t acc = 0;
    const uint4* t4 = (const uint4*)tp;
    for (int i = tid; i < 2048; i += 512) {
        uint4 v = t4[i];
        acc |= (v.x | v.y | v.z | v.w) & 0xFFFFFF00u;
    }
    const uint4* i4 = (const uint4*)ip;
    for (int i = tid; i < 1600; i += 512) {
        uint4 v = i4[i];
        acc |= (v.x | v.y | v.z | v.w) & 0xFFFFFF00u;
    }
    uint32_t any = __ballot_sync(0xffffffffu, acc != 0);
    if ((tid & 31) == 0 && any) atomicOr(&sflag, 1);
    __syncthreads();
    if (tid == 0) g_isU8 = sflag;
}

// ---------------------------------------------------------------------------
// Half-batch GEMM kernel: grid 512 (b = blk>>1, half = blk&1), 256 threads,
// 2 CTAs/SM. Each CTA: 64 m-rows x 104 n, full K. Split-bf16 mma.sync,
// double-buffered staging; epilogue writes A to g_A in ipot blob order.
// Warp w: local row-group r=w>>1 (m 16r..16r+15), slot s=w&1, tiles 7s..
// ---------------------------------------------------------------------------
__global__ void __launch_bounds__(256, 2) k_gemm(const float* __restrict__ seq,
                                                 const unsigned char* __restrict__ tp,
                                                 const unsigned char* __restrict__ ip) {
    extern __shared__ __align__(16) char dsm[];
    __shared__ float pSq[672];                 // 256 X partials + 416 Y partials
    __shared__ float sNxi[64], sNyi[NP];
    __shared__ float sXm[64], sYm[NP];

    const int blk = blockIdx.x;
    const int b = blk >> 1, half = blk & 1;
    const int tid = threadIdx.x;
    const int lane = tid & 31, w = tid >> 5;
    const int g = lane >> 2, q2 = lane & 3;
    const int r = w >> 1, s = w & 1;
    const int TBASE = s * 7, NT = 7 - s;

    uint32_t rawb = smem_u32(dsm);
    uint32_t sb = (rawb + 1023u) & ~1023u;
    char* sbuf = dsm + (sb - rawb);

    const int u8 = g_isU8;
    if (tid < 64) {
        int gm = 64 * half + tid;
        int pad = u8 ? (tp[b * M + gm] != 0) : (((const int*)tp)[b * M + gm] != 0);
        sXm[tid] = pad ? 1e4f : 0.f;
    } else if (tid < 64 + NP) {
        int n = tid - 64;
        int pad = (n >= NIMG) ? 1
                : (u8 ? (ip[b * NIMG + n] != 0) : (((const int*)ip)[b * NIMG + n] != 0));
        sYm[n] = pad ? 1e4f : 0.f;
    }

    const float* seqb = seq + (size_t)b * 228 * D;
    // X unit = tid (64 rows x 4 segs); Y unit A = tid, unit B = tid+256 (tid<160)
    const int xrow = tid >> 2, xseg = tid & 3;
    const float* px = seqb + (size_t)(64 * half + xrow) * D + xseg * 16;
    const uint32_t xsw0 = SWZ((uint32_t)(xrow * 128 + xseg * 32));
    const uint32_t xsw1 = SWZ((uint32_t)(xrow * 128 + xseg * 32 + 16));

    const int yrowA = tid >> 2, ysegA = tid & 3;
    const float* pyA = (yrowA < NIMG)
                     ? (seqb + (size_t)(128 + yrowA) * D + ysegA * 16) : nullptr;
    const uint32_t yswA0 = SWZ((uint32_t)(yrowA * 128 + ysegA * 32));
    const uint32_t yswA1 = SWZ((uint32_t)(yrowA * 128 + ysegA * 32 + 16));

    const int hasB = tid < 160;
    const int uB = tid + 256;
    const int yrowB = uB >> 2, ysegB = uB & 3;
    const float* pyB = (hasB && yrowB < NIMG)
                     ? (seqb + (size_t)(128 + yrowB) * D + ysegB * 16) : nullptr;
    const uint32_t yswB0 = SWZ((uint32_t)(yrowB * 128 + ysegB * 32));
    const uint32_t yswB1 = SWZ((uint32_t)(yrowB * 128 + ysegB * 32 + 16));

    const int j8 = lane >> 3, sub = lane & 7;
    const uint32_t arow_off = (uint32_t)((16 * r + ((j8 & 1) << 3) + sub) * 128);
    const int acol = (j8 >> 1) * 8;
    const int bcol = j8 * 8;

    float acc[28];
#pragma unroll
    for (int i = 0; i < 28; i++) acc[i] = 0.f;
    float naccX = 0.f, naccA = 0.f, naccB = 0.f;

    float4 vx[4], vyA[4], vyB[4];
    {
        const float4* p4 = (const float4*)px;
        vx[0] = p4[0]; vx[1] = p4[1]; vx[2] = p4[2]; vx[3] = p4[3];
        if (pyA) { const float4* q4 = (const float4*)pyA;
                   vyA[0] = q4[0]; vyA[1] = q4[1]; vyA[2] = q4[2]; vyA[3] = q4[3]; }
        else vyA[0] = vyA[1] = vyA[2] = vyA[3] = make_float4(0.f, 0.f, 0.f, 0.f);
        if (hasB) {
            if (pyB) { const float4* q4 = (const float4*)pyB;
                       vyB[0] = q4[0]; vyB[1] = q4[1]; vyB[2] = q4[2]; vyB[3] = q4[3]; }
            else vyB[0] = vyB[1] = vyB[2] = vyB[3] = make_float4(0.f, 0.f, 0.f, 0.f);
        }
    }

    for (int c = 0; c < 12; c++) {
        char* bb = sbuf + (uint32_t)(c & 1) * BUF_BYTES;
        // ---- convert + store + sumsq ----
        {
            float ss = 0.f;
#pragma unroll
            for (int h = 0; h < 2; h++) {
                float4 f0 = vx[2 * h], f1 = vx[2 * h + 1];
                ss += f0.x*f0.x + f0.y*f0.y + f0.z*f0.z + f0.w*f0.w
                    + f1.x*f1.x + f1.y*f1.y + f1.z*f1.z + f1.w*f1.w;
                uint4 hi, lo;
                split2(f0.x, f0.y, hi.x, lo.x);
                split2(f0.z, f0.w, hi.y, lo.y);
                split2(f1.x, f1.y, hi.z, lo.z);
                split2(f1.z, f1.w, hi.w, lo.w);
                uint32_t sw = h ? xsw1 : xsw0;
                *(uint4*)(bb + XHI_OFF + sw) = hi;
                *(uint4*)(bb + XLO_OFF + sw) = lo;
            }
            naccX += ss;
        }
        {
            float ss = 0.f;
#pragma unroll
            for (int h = 0; h < 2; h++) {
                float4 f0 = vyA[2 * h], f1 = vyA[2 * h + 1];
                ss += f0.x*f0.x + f0.y*f0.y + f0.z*f0.z + f0.w*f0.w
                    + f1.x*f1.x + f1.y*f1.y + f1.z*f1.z + f1.w*f1.w;
                uint4 hi, lo;
                split2(f0.x, f0.y, hi.x, lo.x);
                split2(f0.z, f0.w, hi.y, lo.y);
                split2(f1.x, f1.y, hi.z, lo.z);
                split2(f1.z, f1.w, hi.w, lo.w);
                uint32_t sw = h ? yswA1 : yswA0;
                *(uint4*)(bb + YHI_OFF + sw) = hi;
                *(uint4*)(bb + YLO_OFF + sw) = lo;
            }
            naccA += ss;
        }
        if (hasB) {
            float ss = 0.f;
#pragma unroll
            for (int h = 0; h < 2; h++) {
                float4 f0 = vyB[2 * h], f1 = vyB[2 * h + 1];
                ss += f0.x*f0.x + f0.y*f0.y + f0.z*f0.z + f0.w*f0.w
                    + f1.x*f1.x + f1.y*f1.y + f1.z*f1.z + f1.w*f1.w;
                uint4 hi, lo;
                split2(f0.x, f0.y, hi.x, lo.x);
                split2(f0.z, f0.w, hi.y, lo.y);
                split2(f1.x, f1.y, hi.z, lo.z);
                split2(f1.z, f1.w, hi.w, lo.w);
                uint32_t sw = h ? yswB1 : yswB0;
                *(uint4*)(bb + YHI_OFF + sw) = hi;
                *(uint4*)(bb + YLO_OFF + sw) = lo;
            }
            naccB += ss;
        }
        __syncthreads();

        // ---- prefetch next chunk ----
        if (c < 11) {
            const float4* p4 = (const float4*)(px + (c + 1) * 64);
            vx[0] = p4[0]; vx[1] = p4[1]; vx[2] = p4[2]; vx[3] = p4[3];
            if (pyA) { const float4* q4 = (const float4*)(pyA + (c + 1) * 64);
                       vyA[0] = q4[0]; vyA[1] = q4[1]; vyA[2] = q4[2]; vyA[3] = q4[3]; }
            if (hasB && pyB) {
                const float4* q4 = (const float4*)(pyB + (c + 1) * 64);
                vyB[0] = q4[0]; vyB[1] = q4[1]; vyB[2] = q4[2]; vyB[3] = q4[3];
            }
        }

        // ---- tensor-core compute ----
        uint32_t bbase = sb + (uint32_t)(c & 1) * BUF_BYTES;
#pragma unroll
        for (int k0 = 0; k0 < 64; k0 += 32) {
            uint32_t ah0[4], ah1[4], al0[4], al1[4];
            uint32_t offA0 = SWZ(arow_off + (uint32_t)((k0 + acol) * 2));
            uint32_t offA1 = SWZ(arow_off + (uint32_t)((k0 + 16 + acol) * 2));
            ldsm4(bbase + XHI_OFF + offA0, ah0);
            ldsm4(bbase + XHI_OFF + offA1, ah1);
            ldsm4(bbase + XLO_OFF + offA0, al0);
            ldsm4(bbase + XLO_OFF + offA1, al1);
#pragma unroll
            for (int ti = 0; ti < 7; ti++) {
                if (ti < NT) {
                    int t = TBASE + ti;
                    uint32_t offB = SWZ((uint32_t)((8 * t + sub) * 128 + (k0 + bcol) * 2));
                    uint32_t bh[4], bl[4];
                    ldsm4(bbase + YHI_OFF + offB, bh);
                    ldsm4(bbase + YLO_OFF + offB, bl);
                    float* d = &acc[ti * 4];
                    mma_bf16(d, ah0, bh[0], bh[1]);
                    mma_bf16(d, al0, bh[0], bh[1]);
                    mma_bf16(d, ah0, bl[0], bl[1]);
                    mma_bf16(d, ah1, bh[2], bh[3]);
                    mma_bf16(d, al1, bh[2], bh[3]);
                    mma_bf16(d, ah1, bl[2], bl[3]);
                }
            }
        }
    }

    // ---- norms ----
    pSq[tid] = naccX;
    pSq[256 + tid] = naccA;
    if (hasB) pSq[256 + uB] = naccB;
    __syncthreads();
    if (tid < 64) {
        float ss = pSq[4 * tid] + pSq[4 * tid + 1] + pSq[4 * tid + 2] + pSq[4 * tid + 3];
        sNxi[tid] = 1.f / fmaxf(sqrtf(ss), 1e-5f);
    } else if (tid < 64 + NP) {
        int n = tid - 64;
        float ss = pSq[256 + 4 * n] + pSq[256 + 4 * n + 1]
                 + pSq[256 + 4 * n + 2] + pSq[256 + 4 * n + 3];
        sNyi[n] = 1.f / fmaxf(sqrtf(ss), 1e-5f);
    }
    __syncthreads();

    // ---- epilogue -> g_A blob (ipot order): rg = half*4 + r ----
    const int m0 = 16 * r + g, m1 = m0 + 8;   // local rows
    const float xm0 = sXm[m0], xm1 = sXm[m1];
    const float nx0 = sNxi[m0], nx1 = sNxi[m1];
    float* gAout = g_A + (((size_t)b * 8 + (half * 4 + r)) * 13 + TBASE) * 128;
#pragma unroll
    for (int ti = 0; ti < 7; ti++) {
        if (ti < NT) {
            int t = TBASE + ti;
            int n0 = 8 * t + 2 * q2, n1 = n0 + 1;
            float ny0 = sNyi[n0], ny1 = sNyi[n1];
            float ym0 = sYm[n0],  ym1 = sYm[n1];
            float4 a;
            a.x = (xm0 > 0.f || ym0 > 0.f) ? 0.f
                : __expf(2.f * (acc[ti * 4 + 0] * nx0 * ny0 - 1.f));
            a.y = (xm0 > 0.f || ym1 > 0.f) ? 0.f
                : __expf(2.f * (acc[ti * 4 + 1] * nx0 * ny1 - 1.f));
            a.z = (xm1 > 0.f || ym0 > 0.f) ? 0.f
                : __expf(2.f * (acc[ti * 4 + 2] * nx1 * ny0 - 1.f));
            a.w = (xm1 > 0.f || ym1 > 0.f) ? 0.f
                : __expf(2.f * (acc[ti * 4 + 3] * nx1 * ny1 - 1.f));
            *(float4*)(gAout + ti * 128 + lane * 4) = a;
        }
    }
}

// ---------------------------------------------------------------------------
// IPOT kernel (unchanged from R8): 256 threads, 2 CTAs/SM, A in smem,
// Q register-resident, smem-partial qs reduction (no shuffles).
// ---------------------------------------------------------------------------
__global__ void __launch_bounds__(256, 2) k_ipot(const unsigned char* __restrict__ tp,
                                                 const unsigned char* __restrict__ ip) {
    extern __shared__ __align__(16) float sA[];   // NP*M floats
    __shared__ __align__(16) float sQP[NP * QP_STRIDE];
    __shared__ float sXm[M], sYm[NP];
    __shared__ __align__(8) float sDelta[NP];
    __shared__ float sRed[8];
    __shared__ int sCx, sCy;

    const int b = blockIdx.x, tid = threadIdx.x;
    const int lane = tid & 31, w = tid >> 5;
    const int g = lane >> 2, q2 = lane & 3;
    const int col = 8 * w + g;

    if (tid == 0) { sCx = 0; sCy = 0; }
    __syncthreads();
    const int u8 = g_isU8;
    if (tid < M) {
        int pad = u8 ? (tp[b * M + tid] != 0) : (((const int*)tp)[b * M + tid] != 0);
        sXm[tid] = pad ? 1e4f : 0.f;
        if (pad) atomicAdd(&sCx, 1);
    }
    if (tid < NP) {
        int pad = (tid >= NIMG) ? 1
                : (u8 ? (ip[b * NIMG + tid] != 0) : (((const int*)ip)[b * NIMG + tid] != 0));
        sYm[tid] = pad ? 1e4f : 0.f;
        if (pad && tid < NIMG) atomicAdd(&sCy, 1);
    }

    const float4* gA4 = (const float4*)(g_A + (size_t)b * (NP * M));
    float4* sA4 = (float4*)sA;
#pragma unroll
    for (int k = 0; k < 13; k++) sA4[k * 256 + tid] = gA4[k * 256 + tid];
    __syncthreads();

    const float4* myA = sA4 + w * 13 * 32 + lane;
    float Qr[52];
#pragma unroll
    for (int t = 0; t < 13; t++) {
        float4 a = myA[t * 32];
        Qr[t * 4 + 0] = a.x; Qr[t * 4 + 1] = a.y;
        Qr[t * 4 + 2] = a.z; Qr[t * 4 + 3] = a.w;
    }

    const int m0 = 16 * w + g, m1 = m0 + 8;
    const float xm0 = sXm[m0], xm1 = sXm[m1];
    const float xl = (float)(M - sCx), yl = (float)(NIMG - sCy);

    float sig0 = xm0 > 0.f ? 0.f : 1.f / xl;
    float sig1 = xm1 > 0.f ? 0.f : 1.f / xl;

#pragma unroll
    for (int t = 0; t < 13; t++) {
        int n0 = 8 * t + 2 * q2;
        sQP[n0 * QP_STRIDE + col]       = Qr[t * 4 + 0] * sig0 + Qr[t * 4 + 2] * sig1;
        sQP[(n0 + 1) * QP_STRIDE + col] = Qr[t * 4 + 1] * sig0 + Qr[t * 4 + 3] * sig1;
    }
    __syncthreads();

    float ot = 0.f;
#pragma unroll 1
    for (int it = 0; it < ITERS; it++) {
        if (tid < NP) {
            const float4* rp = (const float4*)&sQP[tid * QP_STRIDE];
            float4 r0 = rp[0], r1 = rp[1], r2 = rp[2], r3 = rp[3];
#pragma unroll
            for (int j = 4; j < 16; j += 4) {
                float4 v0 = rp[j], v1 = rp[j + 1], v2 = rp[j + 2], v3 = rp[j + 3];
                r0.x += v0.x; r0.y += v0.y; r0.z += v0.z; r0.w += v0.w;
                r1.x += v1.x; r1.y += v1.y; r1.z += v1.z; r1.w += v1.w;
                r2.x += v2.x; r2.y += v2.y; r2.z += v2.z; r2.w += v2.w;
                r3.x += v3.x; r3.y += v3.y; r3.z += v3.z; r3.w += v3.w;
            }
            float qs = (r0.x + r0.y + r0.z + r0.w) + (r1.x + r1.y + r1.z + r1.w)
                     + (r2.x + r2.y + r2.z + r2.w) + (r3.x + r3.y + r3.z + r3.w);
            sDelta[tid] = __fdividef(1.f, yl * qs + sYm[tid]);
        }
        __syncthreads();

        float2 dl[13];
        float p0 = 0.f, p1 = 0.f;
#pragma unroll
        for (int t = 0; t < 13; t++) {
            dl[t] = *(const float2*)&sDelta[8 * t + 2 * q2];
            p0 += dl[t].x * Qr[t * 4 + 0] + dl[t].y * Qr[t * 4 + 1];
            p1 += dl[t].x * Qr[t * 4 + 2] + dl[t].y * Qr[t * 4 + 3];
        }
        p0 += __shfl_xor_sync(0xffffffffu, p0, 1);
        p0 += __shfl_xor_sync(0xffffffffu, p0, 2);
        p1 += __shfl_xor_sync(0xffffffffu, p1, 1);
        p1 += __shfl_xor_sync(0xffffffffu, p1, 2);
        sig0 = __fdividef(1.f, xl * p0 + xm0);
        sig1 = __fdividef(1.f, xl * p1 + xm1);

        if (it < ITERS - 1) {
#pragma unroll
            for (int t = 0; t < 13; t++) {
                float4 a = myA[t * 32];
                float q0 = a.x * Qr[t * 4 + 0] * (dl[t].x * sig0);
                float q1 = a.y * Qr[t * 4 + 1] * (dl[t].y * sig0);
                float q2v = a.z * Qr[t * 4 + 2] * (dl[t].x * sig1);
                float q3 = a.w * Qr[t * 4 + 3] * (dl[t].y * sig1);
                Qr[t * 4 + 0] = q0; Qr[t * 4 + 1] = q1;
                Qr[t * 4 + 2] = q2v; Qr[t * 4 + 3] = q3;
                int n0 = 8 * t + 2 * q2;
                sQP[n0 * QP_STRIDE + col]       = q0 * sig0 + q2v * sig1;
                sQP[(n0 + 1) * QP_STRIDE + col] = q1 * sig0 + q3 * sig1;
            }
        } else {
#pragma unroll
            for (int t = 0; t < 13; t++) {
                float4 a = myA[t * 32];
                if (a.x > 0.f) ot += (-0.5f * __logf(a.x)) * Qr[t * 4 + 0] * dl[t].x * sig0;
                if (a.y > 0.f) ot += (-0.5f * __logf(a.y)) * Qr[t * 4 + 1] * dl[t].y * sig0;
                if (a.z > 0.f) ot += (-0.5f * __logf(a.z)) * Qr[t * 4 + 2] * dl[t].x * sig1;
                if (a.w > 0.f) ot += (-0.5f * __logf(a.w)) * Qr[t * 4 + 3] * dl[t].y * sig1;
            }
        }
        __syncthreads();
    }

    ot += __shfl_xor_sync(0xffffffffu, ot, 16);
    ot += __shfl_xor_sync(0xffffffffu, ot, 8);
    ot += __shfl_xor_sync(0xffffffffu, ot, 4);
    ot += __shfl_xor_sync(0xffffffffu, ot, 2);
    ot += __shfl_xor_sync(0xffffffffu, ot, 1);
    if (lane == 0) sRed[w] = ot;
    __syncthreads();
    if (tid == 0) {
        float sum = 0.f;
#pragma unroll
        for (int ww = 0; ww < 8; ww++) sum += sRed[ww];
        g_ot[b] = sum;
    }
}

// ---------------------------------------------------------------------------
// Final signed batch reduction -> scalar loss.
// ---------------------------------------------------------------------------
__global__ void k_final(const int* __restrict__ isc, float* __restrict__ out) {
    int t = threadIdx.x;
    __shared__ float sRed[8];
    float v = g_ot[t];
    float s = (isc[t] == 1) ? v : -v;
    s += __shfl_xor_sync(0xffffffffu, s, 16);
    s += __shfl_xor_sync(0xffffffffu, s, 8);
    s += __shfl_xor_sync(0xffffffffu, s, 4);
    s += __shfl_xor_sync(0xffffffffu, s, 2);
    s += __shfl_xor_sync(0xffffffffu, s, 1);
    if ((t & 31) == 0) sRed[t >> 5] = s;
    __syncthreads();
    if (t == 0) {
        float tot = 0.f;
#pragma unroll
        for (int w = 0; w < 8; w++) tot += sRed[w];
        out[0] = tot / (float)BATCH;
    }
}

// ---------------------------------------------------------------------------
extern "C" void kernel_launch(void* const* d_in, const int* in_sizes, int n_in,
                              void* d_out, int out_size) {
    const float* seq = (const float*)d_in[0];
    const unsigned char* tp = (const unsigned char*)d_in[3];
    const unsigned char* ip = (const unsigned char*)d_in[4];
    const int* isc = (const int*)d_in[5];
    float* out = (float*)d_out;

    cudaFuncSetAttribute(k_gemm, cudaFuncAttributeMaxDynamicSharedMemorySize,
                         DSM_GEMM);
    cudaFuncSetAttribute(k_ipot, cudaFuncAttributeMaxDynamicSharedMemorySize,
                         DSM_IPOT);

    k_detect<<<1, 512>>>(tp, ip);
    k_nop<<<1, 32>>>();
    k_nop<<<1, 32>>>();   // spacers: k_gemm is profiled launch #4
    k_gemm<<<2 * BATCH, 256, DSM_GEMM>>>(seq, tp, ip);
    k_ipot<<<BATCH, 256, DSM_IPOT>>>(tp, ip);
    k_final<<<1, 256>>>(isc, out);
}

// round 10
// speedup vs baseline: 1.2992x; 1.0066x over previous
#include <cuda_runtime.h>
#include <cuda_bf16.h>
#include <stdint.h>

// Problem constants
#define BATCH 256
#define M 128
#define NIMG 100
#define NP 104          // 13 * 8
#define D 768
#define ITERS 50

// Half-batch GEMM staging (per buffer, swizzled bf16, 128B rows)
#define XHI_OFF 0u
#define XLO_OFF 8192u
#define YHI_OFF 16384u
#define YLO_OFF 29696u
#define BUF_BYTES 43008u
#define DSM_GEMM (2 * 43008 + 1024)
#define DSM_IPOT (NP * M * 4)     // 53248: A matrix blob

#define QP_STRIDE 68              // 64 partial cols + 4 pad floats

#define SWZ(o) ((o) ^ (((o) >> 3) & 0x70))

// A stored as fragment blob in ipot geometry:
// g_A[((b*8 + rg)*13 + t)*128 + lane*4 + e], rg = m-row-group 0..7
__device__ __align__(16) float g_A[BATCH * 8 * 13 * 128];
__device__ float g_ot[BATCH];
__device__ int   g_isU8;

// ---------------------------------------------------------------------------
// Helpers
// ---------------------------------------------------------------------------
__device__ __forceinline__ uint32_t smem_u32(const void* p) {
    uint32_t a;
    asm("{ .reg .u64 t; cvta.to.shared.u64 t, %1; cvt.u32.u64 %0, t; }"
        : "=r"(a) : "l"(p));
    return a;
}
__device__ __forceinline__ void ldsm4(uint32_t addr, uint32_t* r) {
    asm volatile("ldmatrix.sync.aligned.m8n8.x4.shared.b16 {%0,%1,%2,%3}, [%4];"
                 : "=r"(r[0]), "=r"(r[1]), "=r"(r[2]), "=r"(r[3]) : "r"(addr));
}
__device__ __forceinline__ void mma_bf16(float* d, const uint32_t* a,
                                         uint32_t b0, uint32_t b1) {
    asm volatile(
        "mma.sync.aligned.m16n8k16.row.col.f32.bf16.bf16.f32 "
        "{%0,%1,%2,%3},{%4,%5,%6,%7},{%8,%9},{%0,%1,%2,%3};"
        : "+f"(d[0]), "+f"(d[1]), "+f"(d[2]), "+f"(d[3])
        : "r"(a[0]), "r"(a[1]), "r"(a[2]), "r"(a[3]), "r"(b0), "r"(b1));
}
__device__ __forceinline__ void split2(float a, float b, uint32_t& hi, uint32_t& lo) {
    asm("cvt.rn.bf16x2.f32 %0, %1, %2;" : "=r"(hi) : "f"(b), "f"(a));
    float ah = __uint_as_float(hi << 16);
    float bh = __uint_as_float(hi & 0xffff0000u);
    float la = a - ah, lb = b - bh;
    asm("cvt.rn.bf16x2.f32 %0, %1, %2;" : "=r"(lo) : "f"(lb), "f"(la));
}

// Convert 4 float4 (one 64-elem row-chunk) to hi/lo bf16, store swizzled,
// return sum of squares. Transient registers only.
__device__ __forceinline__ float conv_store(char* bb, uint32_t hiOff, uint32_t loOff,
                                            uint32_t sw0, uint32_t sw1,
                                            float4 f0, float4 f1,
                                            float4 f2, float4 f3) {
    float ss = f0.x*f0.x + f0.y*f0.y + f0.z*f0.z + f0.w*f0.w
             + f1.x*f1.x + f1.y*f1.y + f1.z*f1.z + f1.w*f1.w
             + f2.x*f2.x + f2.y*f2.y + f2.z*f2.z + f2.w*f2.w
             + f3.x*f3.x + f3.y*f3.y + f3.z*f3.z + f3.w*f3.w;
    uint4 hi, lo;
    split2(f0.x, f0.y, hi.x, lo.x);
    split2(f0.z, f0.w, hi.y, lo.y);
    split2(f1.x, f1.y, hi.z, lo.z);
    split2(f1.z, f1.w, hi.w, lo.w);
    *(uint4*)(bb + hiOff + sw0) = hi;
    *(uint4*)(bb + loOff + sw0) = lo;
    split2(f2.x, f2.y, hi.x, lo.x);
    split2(f2.z, f2.w, hi.y, lo.y);
    split2(f3.x, f3.y, hi.z, lo.z);
    split2(f3.z, f3.w, hi.w, lo.w);
    *(uint4*)(bb + hiOff + sw1) = hi;
    *(uint4*)(bb + loOff + sw1) = lo;
    return ss;
}

__global__ void k_nop() {}

// ---------------------------------------------------------------------------
// Pad-dtype detect (uint8-bool vs int32)
// ---------------------------------------------------------------------------
__global__ void __launch_bounds__(512) k_detect(const unsigned char* __restrict__ tp,
                                                const unsigned char* __restrict__ ip) {
    __shared__ int sflag;
    int tid = threadIdx.x;
    if (tid == 0) sflag = 0;
    __syncthreads();
    uint32_t acc = 0;
    const uint4* t4 = (const uint4*)tp;
    for (int i = tid; i < 2048; i += 512) {
        uint4 v = t4[i];
        acc |= (v.x | v.y | v.z | v.w) & 0xFFFFFF00u;
    }
    const uint4* i4 = (const uint4*)ip;
    for (int i = tid; i < 1600; i += 512) {
        uint4 v = i4[i];
        acc |= (v.x | v.y | v.z | v.w) & 0xFFFFFF00u;
    }
    uint32_t any = __ballot_sync(0xffffffffu, acc != 0);
    if ((tid & 31) == 0 && any) atomicOr(&sflag, 1);
    __syncthreads();
    if (tid == 0) g_isU8 = sflag;
}

// ---------------------------------------------------------------------------
// Half-batch GEMM: grid 512 (b = blk>>1, half = blk&1), 256 threads, 2 CTAs/SM.
// Staging loads are DIRECT (transient registers, MLP=12) — no persistent
// prefetch arrays, so no spills; co-resident CTA hides the per-chunk latency.
// ---------------------------------------------------------------------------
__global__ void __launch_bounds__(256, 2) k_gemm(const float* __restrict__ seq,
                                                 const unsigned char* __restrict__ tp,
                                                 const unsigned char* __restrict__ ip) {
    extern __shared__ __align__(16) char dsm[];
    __shared__ float pSq[672];
    __shared__ float sNxi[64], sNyi[NP];
    __shared__ float sXm[64], sYm[NP];

    const int blk = blockIdx.x;
    const int b = blk >> 1, half = blk & 1;
    const int tid = threadIdx.x;
    const int lane = tid & 31, w = tid >> 5;
    const int g = lane >> 2, q2 = lane & 3;
    const int r = w >> 1, s = w & 1;
    const int TBASE = s * 7, NT = 7 - s;

    uint32_t rawb = smem_u32(dsm);
    uint32_t sb = (rawb + 1023u) & ~1023u;
    char* sbuf = dsm + (sb - rawb);

    const int u8 = g_isU8;
    if (tid < 64) {
        int gm = 64 * half + tid;
        int pad = u8 ? (tp[b * M + gm] != 0) : (((const int*)tp)[b * M + gm] != 0);
        sXm[tid] = pad ? 1e4f : 0.f;
    } else if (tid < 64 + NP) {
        int n = tid - 64;
        int pad = (n >= NIMG) ? 1
                : (u8 ? (ip[b * NIMG + n] != 0) : (((const int*)ip)[b * NIMG + n] != 0));
        sYm[n] = pad ? 1e4f : 0.f;
    }

    const float* seqb = seq + (size_t)b * 228 * D;
    const int xrow = tid >> 2, xseg = tid & 3;
    const float* px = seqb + (size_t)(64 * half + xrow) * D + xseg * 16;
    const uint32_t xsw0 = SWZ((uint32_t)(xrow * 128 + xseg * 32));
    const uint32_t xsw1 = SWZ((uint32_t)(xrow * 128 + xseg * 32 + 16));

    const int yrowA = tid >> 2, ysegA = tid & 3;
    const float* pyA = (yrowA < NIMG)
                     ? (seqb + (size_t)(128 + yrowA) * D + ysegA * 16) : nullptr;
    const uint32_t yswA0 = SWZ((uint32_t)(yrowA * 128 + ysegA * 32));
    const uint32_t yswA1 = SWZ((uint32_t)(yrowA * 128 + ysegA * 32 + 16));

    const int hasB = tid < 160;
    const int uB = tid + 256;
    const int yrowB = uB >> 2, ysegB = uB & 3;
    const float* pyB = (hasB && yrowB < NIMG)
                     ? (seqb + (size_t)(128 + yrowB) * D + ysegB * 16) : nullptr;
    const uint32_t yswB0 = SWZ((uint32_t)(yrowB * 128 + ysegB * 32));
    const uint32_t yswB1 = SWZ((uint32_t)(yrowB * 128 + ysegB * 32 + 16));

    const int j8 = lane >> 3, sub = lane & 7;
    const uint32_t arow_off = (uint32_t)((16 * r + ((j8 & 1) << 3) + sub) * 128);
    const int acol = (j8 >> 1) * 8;
    const int bcol = j8 * 8;

    float acc[28];
#pragma unroll
    for (int i = 0; i < 28; i++) acc[i] = 0.f;
    float naccX = 0.f, naccA = 0.f, naccB = 0.f;

    for (int c = 0; c < 12; c++) {
        char* bb = sbuf + (uint32_t)(c & 1) * BUF_BYTES;

        // ---- direct loads (transient, high MLP) ----
        float4 x0, x1, x2, x3, a0, a1, a2, a3, y0, y1, y2, y3;
        {
            const float4* p4 = (const float4*)px + c * 16;
            x0 = p4[0]; x1 = p4[1]; x2 = p4[2]; x3 = p4[3];
        }
        if (pyA) {
            const float4* q4 = (const float4*)pyA + c * 16;
            a0 = q4[0]; a1 = q4[1]; a2 = q4[2]; a3 = q4[3];
        } else {
            a0 = a1 = a2 = a3 = make_float4(0.f, 0.f, 0.f, 0.f);
        }
        if (hasB) {
            if (pyB) {
                const float4* q4 = (const float4*)pyB + c * 16;
                y0 = q4[0]; y1 = q4[1]; y2 = q4[2]; y3 = q4[3];
            } else {
                y0 = y1 = y2 = y3 = make_float4(0.f, 0.f, 0.f, 0.f);
            }
        }

        // ---- convert + store + sumsq ----
        naccX += conv_store(bb, XHI_OFF, XLO_OFF, xsw0, xsw1, x0, x1, x2, x3);
        naccA += conv_store(bb, YHI_OFF, YLO_OFF, yswA0, yswA1, a0, a1, a2, a3);
        if (hasB)
            naccB += conv_store(bb, YHI_OFF, YLO_OFF, yswB0, yswB1, y0, y1, y2, y3);
        __syncthreads();

        // ---- tensor-core compute ----
        uint32_t bbase = sb + (uint32_t)(c & 1) * BUF_BYTES;
#pragma unroll
        for (int k0 = 0; k0 < 64; k0 += 32) {
            uint32_t ah0[4], ah1[4], al0[4], al1[4];
            uint32_t offA0 = SWZ(arow_off + (uint32_t)((k0 + acol) * 2));
            uint32_t offA1 = SWZ(arow_off + (uint32_t)((k0 + 16 + acol) * 2));
            ldsm4(bbase + XHI_OFF + offA0, ah0);
            ldsm4(bbase + XHI_OFF + offA1, ah1);
            ldsm4(bbase + XLO_OFF + offA0, al0);
            ldsm4(bbase + XLO_OFF + offA1, al1);
#pragma unroll
            for (int ti = 0; ti < 7; ti++) {
                if (ti < NT) {
                    int t = TBASE + ti;
                    uint32_t offB = SWZ((uint32_t)((8 * t + sub) * 128 + (k0 + bcol) * 2));
                    uint32_t bh[4], bl[4];
                    ldsm4(bbase + YHI_OFF + offB, bh);
                    ldsm4(bbase + YLO_OFF + offB, bl);
                    float* d = &acc[ti * 4];
                    mma_bf16(d, ah0, bh[0], bh[1]);
                    mma_bf16(d, al0, bh[0], bh[1]);
                    mma_bf16(d, ah0, bl[0], bl[1]);
                    mma_bf16(d, ah1, bh[2], bh[3]);
                    mma_bf16(d, al1, bh[2], bh[3]);
                    mma_bf16(d, ah1, bl[2], bl[3]);
                }
            }
        }
    }

    // ---- norms ----
    pSq[tid] = naccX;
    pSq[256 + tid] = naccA;
    if (hasB) pSq[256 + uB] = naccB;
    __syncthreads();
    if (tid < 64) {
        float ss = pSq[4 * tid] + pSq[4 * tid + 1] + pSq[4 * tid + 2] + pSq[4 * tid + 3];
        sNxi[tid] = 1.f / fmaxf(sqrtf(ss), 1e-5f);
    } else if (tid < 64 + NP) {
        int n = tid - 64;
        float ss = pSq[256 + 4 * n] + pSq[256 + 4 * n + 1]
                 + pSq[256 + 4 * n + 2] + pSq[256 + 4 * n + 3];
        sNyi[n] = 1.f / fmaxf(sqrtf(ss), 1e-5f);
    }
    __syncthreads();

    // ---- epilogue -> g_A blob (ipot order): rg = half*4 + r ----
    const int m0 = 16 * r + g, m1 = m0 + 8;
    const float xm0 = sXm[m0], xm1 = sXm[m1];
    const float nx0 = sNxi[m0], nx1 = sNxi[m1];
    float* gAout = g_A + (((size_t)b * 8 + (half * 4 + r)) * 13 + TBASE) * 128;
#pragma unroll
    for (int ti = 0; ti < 7; ti++) {
        if (ti < NT) {
            int t = TBASE + ti;
            int n0 = 8 * t + 2 * q2, n1 = n0 + 1;
            float ny0 = sNyi[n0], ny1 = sNyi[n1];
            float ym0 = sYm[n0],  ym1 = sYm[n1];
            float4 a;
            a.x = (xm0 > 0.f || ym0 > 0.f) ? 0.f
                : __expf(2.f * (acc[ti * 4 + 0] * nx0 * ny0 - 1.f));
            a.y = (xm0 > 0.f || ym1 > 0.f) ? 0.f
                : __expf(2.f * (acc[ti * 4 + 1] * nx0 * ny1 - 1.f));
            a.z = (xm1 > 0.f || ym0 > 0.f) ? 0.f
                : __expf(2.f * (acc[ti * 4 + 2] * nx1 * ny0 - 1.f));
            a.w = (xm1 > 0.f || ym1 > 0.f) ? 0.f
                : __expf(2.f * (acc[ti * 4 + 3] * nx1 * ny1 - 1.f));
            *(float4*)(gAout + ti * 128 + lane * 4) = a;
        }
    }
}

// ---------------------------------------------------------------------------
// IPOT kernel (unchanged from R8): 256 threads, 2 CTAs/SM, A in smem,
// Q register-resident, smem-partial qs reduction (no shuffles).
// ---------------------------------------------------------------------------
__global__ void __launch_bounds__(256, 2) k_ipot(const unsigned char* __restrict__ tp,
                                                 const unsigned char* __restrict__ ip) {
    extern __shared__ __align__(16) float sA[];   // NP*M floats
    __shared__ __align__(16) float sQP[NP * QP_STRIDE];
    __shared__ float sXm[M], sYm[NP];
    __shared__ __align__(8) float sDelta[NP];
    __shared__ float sRed[8];
    __shared__ int sCx, sCy;

    const int b = blockIdx.x, tid = threadIdx.x;
    const int lane = tid & 31, w = tid >> 5;
    const int g = lane >> 2, q2 = lane & 3;
    const int col = 8 * w + g;

    if (tid == 0) { sCx = 0; sCy = 0; }
    __syncthreads();
    const int u8 = g_isU8;
    if (tid < M) {
        int pad = u8 ? (tp[b * M + tid] != 0) : (((const int*)tp)[b * M + tid] != 0);
        sXm[tid] = pad ? 1e4f : 0.f;
        if (pad) atomicAdd(&sCx, 1);
    }
    if (tid < NP) {
        int pad = (tid >= NIMG) ? 1
                : (u8 ? (ip[b * NIMG + tid] != 0) : (((const int*)ip)[b * NIMG + tid] != 0));
        sYm[tid] = pad ? 1e4f : 0.f;
        if (pad && tid < NIMG) atomicAdd(&sCy, 1);
    }

    const float4* gA4 = (const float4*)(g_A + (size_t)b * (NP * M));
    float4* sA4 = (float4*)sA;
#pragma unroll
    for (int k = 0; k < 13; k++) sA4[k * 256 + tid] = gA4[k * 256 + tid];
    __syncthreads();

    const float4* myA = sA4 + w * 13 * 32 + lane;
    float Qr[52];
#pragma unroll
    for (int t = 0; t < 13; t++) {
        float4 a = myA[t * 32];
        Qr[t * 4 + 0] = a.x; Qr[t * 4 + 1] = a.y;
        Qr[t * 4 + 2] = a.z; Qr[t * 4 + 3] = a.w;
    }

    const int m0 = 16 * w + g, m1 = m0 + 8;
    const float xm0 = sXm[m0], xm1 = sXm[m1];
    const float xl = (float)(M - sCx), yl = (float)(NIMG - sCy);

    float sig0 = xm0 > 0.f ? 0.f : 1.f / xl;
    float sig1 = xm1 > 0.f ? 0.f : 1.f / xl;

#pragma unroll
    for (int t = 0; t < 13; t++) {
        int n0 = 8 * t + 2 * q2;
        sQP[n0 * QP_STRIDE + col]       = Qr[t * 4 + 0] * sig0 + Qr[t * 4 + 2] * sig1;
        sQP[(n0 + 1) * QP_STRIDE + col] = Qr[t * 4 + 1] * sig0 + Qr[t * 4 + 3] * sig1;
    }
    __syncthreads();

    float ot = 0.f;
#pragma unroll 1
    for (int it = 0; it < ITERS; it++) {
        if (tid < NP) {
            const float4* rp = (const float4*)&sQP[tid * QP_STRIDE];
            float4 r0 = rp[0], r1 = rp[1], r2 = rp[2], r3 = rp[3];
#pragma unroll
            for (int j = 4; j < 16; j += 4) {
                float4 v0 = rp[j], v1 = rp[j + 1], v2 = rp[j + 2], v3 = rp[j + 3];
                r0.x += v0.x; r0.y += v0.y; r0.z += v0.z; r0.w += v0.w;
                r1.x += v1.x; r1.y += v1.y; r1.z += v1.z; r1.w += v1.w;
                r2.x += v2.x; r2.y += v2.y; r2.z += v2.z; r2.w += v2.w;
                r3.x += v3.x; r3.y += v3.y; r3.z += v3.z; r3.w += v3.w;
            }
            float qs = (r0.x + r0.y + r0.z + r0.w) + (r1.x + r1.y + r1.z + r1.w)
                     + (r2.x + r2.y + r2.z + r2.w) + (r3.x + r3.y + r3.z + r3.w);
            sDelta[tid] = __fdividef(1.f, yl * qs + sYm[tid]);
        }
        __syncthreads();

        float2 dl[13];
        float p0 = 0.f, p1 = 0.f;
#pragma unroll
        for (int t = 0; t < 13; t++) {
            dl[t] = *(const float2*)&sDelta[8 * t + 2 * q2];
            p0 += dl[t].x * Qr[t * 4 + 0] + dl[t].y * Qr[t * 4 + 1];
            p1 += dl[t].x * Qr[t * 4 + 2] + dl[t].y * Qr[t * 4 + 3];
        }
        p0 += __shfl_xor_sync(0xffffffffu, p0, 1);
        p0 += __shfl_xor_sync(0xffffffffu, p0, 2);
        p1 += __shfl_xor_sync(0xffffffffu, p1, 1);
        p1 += __shfl_xor_sync(0xffffffffu, p1, 2);
        sig0 = __fdividef(1.f, xl * p0 + xm0);
        sig1 = __fdividef(1.f, xl * p1 + xm1);

        if (it < ITERS - 1) {
#pragma unroll
            for (int t = 0; t < 13; t++) {
                float4 a = myA[t * 32];
                float q0 = a.x * Qr[t * 4 + 0] * (dl[t].x * sig0);
                float q1 = a.y * Qr[t * 4 + 1] * (dl[t].y * sig0);
                float q2v = a.z * Qr[t * 4 + 2] * (dl[t].x * sig1);
                float q3 = a.w * Qr[t * 4 + 3] * (dl[t].y * sig1);
                Qr[t * 4 + 0] = q0; Qr[t * 4 + 1] = q1;
                Qr[t * 4 + 2] = q2v; Qr[t * 4 + 3] = q3;
                int n0 = 8 * t + 2 * q2;
                sQP[n0 * QP_STRIDE + col]       = q0 * sig0 + q2v * sig1;
                sQP[(n0 + 1) * QP_STRIDE + col] = q1 * sig0 + q3 * sig1;
            }
        } else {
#pragma unroll
            for (int t = 0; t < 13; t++) {
                float4 a = myA[t * 32];
                if (a.x > 0.f) ot += (-0.5f * __logf(a.x)) * Qr[t * 4 + 0] * dl[t].x * sig0;
                if (a.y > 0.f) ot += (-0.5f * __logf(a.y)) * Qr[t * 4 + 1] * dl[t].y * sig0;
                if (a.z > 0.f) ot += (-0.5f * __logf(a.z)) * Qr[t * 4 + 2] * dl[t].x * sig1;
                if (a.w > 0.f) ot += (-0.5f * __logf(a.w)) * Qr[t * 4 + 3] * dl[t].y * sig1;
            }
        }
        __syncthreads();
    }

    ot += __shfl_xor_sync(0xffffffffu, ot, 16);
    ot += __shfl_xor_sync(0xffffffffu, ot, 8);
    ot += __shfl_xor_sync(0xffffffffu, ot, 4);
    ot += __shfl_xor_sync(0xffffffffu, ot, 2);
    ot += __shfl_xor_sync(0xffffffffu, ot, 1);
    if (lane == 0) sRed[w] = ot;
    __syncthreads();
    if (tid == 0) {
        float sum = 0.f;
#pragma unroll
        for (int ww = 0; ww < 8; ww++) sum += sRed[ww];
        g_ot[b] = sum;
    }
}

// ---------------------------------------------------------------------------
// Final signed batch reduction -> scalar loss.
// ---------------------------------------------------------------------------
__global__ void k_final(const int* __restrict__ isc, float* __restrict__ out) {
    int t = threadIdx.x;
    __shared__ float sRed[8];
    float v = g_ot[t];
    float s = (isc[t] == 1) ? v : -v;
    s += __shfl_xor_sync(0xffffffffu, s, 16);
    s += __shfl_xor_sync(0xffffffffu, s, 8);
    s += __shfl_xor_sync(0xffffffffu, s, 4);
    s += __shfl_xor_sync(0xffffffffu, s, 2);
    s += __shfl_xor_sync(0xffffffffu, s, 1);
    if ((t & 31) == 0) sRed[t >> 5] = s;
    __syncthreads();
    if (t == 0) {
        float tot = 0.f;
#pragma unroll
        for (int w = 0; w < 8; w++) tot += sRed[w];
        out[0] = tot / (float)BATCH;
    }
}

// ---------------------------------------------------------------------------
extern "C" void kernel_launch(void* const* d_in, const int* in_sizes, int n_in,
                              void* d_out, int out_size) {
    const float* seq = (const float*)d_in[0];
    const unsigned char* tp = (const unsigned char*)d_in[3];
    const unsigned char* ip = (const unsigned char*)d_in[4];
    const int* isc = (const int*)d_in[5];
    float* out = (float*)d_out;

    cudaFuncSetAttribute(k_gemm, cudaFuncAttributeMaxDynamicSharedMemorySize,
                         DSM_GEMM);
    cudaFuncSetAttribute(k_ipot, cudaFuncAttributeMaxDynamicSharedMemorySize,
                         DSM_IPOT);

    k_detect<<<1, 512>>>(tp, ip);
    k_nop<<<1, 32>>>();
    k_nop<<<1, 32>>>();   // spacers: k_gemm is profiled launch #4
    k_gemm<<<2 * BATCH, 256, DSM_GEMM>>>(seq, tp, ip);
    k_ipot<<<BATCH, 256, DSM_IPOT>>>(tp, ip);
    k_final<<<1, 256>>>(isc, out);
}